// round 9
// baseline (speedup 1.0000x reference)
#include <cuda_runtime.h>
#include <cuda_bf16.h>
#include <math.h>

// ---------------- problem constants ----------------
#define S_   1024
#define H_   32
#define KVH_ 8
#define DH_  128
#define D_   4096
#define CB_  16
#define NC_  64        // S/CB
#define SB_  16
#define NSEL_ 4
#define WIN_ 64
#define NQKV_ 6144     // H*DH + 2*KVH*DH
#define CDIM_ 2048     // CB*DH
#define NEGF (-3.402823466e38f)
#define SCALE_ 0.08838834764831844056f  // 128^-0.5

// ---------------- scratch (no allocs allowed) ----------------
__device__ float g_qkv [S_ * NQKV_];
__device__ float g_rq  [S_ * H_ * DH_];
__device__ float g_rk  [S_ * KVH_ * DH_];
__device__ float g_ckin[KVH_ * NC_ * CDIM_];
__device__ float g_cvin[KVH_ * NC_ * CDIM_];
__device__ float g_h1  [KVH_ * NC_ * CDIM_];
__device__ float g_ckb [KVH_ * NC_ * DH_];
__device__ float g_cvb [KVH_ * NC_ * DH_];
__device__ float g_ck  [KVH_ * (NC_ + 1) * DH_];
__device__ float g_cv  [KVH_ * (NC_ + 1) * DH_];
__device__ float g_cout[S_ * H_ * DH_];
__device__ float g_fout[S_ * H_ * DH_];
__device__ float g_sout[S_ * H_ * DH_];
__device__ int   g_sel [KVH_ * S_ * 5];
__device__ int   g_selok[KVH_ * S_ * 4];
__device__ float g_gates[S_ * 96];
__device__ float g_mid [S_ * D_];
__device__ float g_part[16 * 1024 * 96];   // split-K partials (max: gates)

// hi/lo tf32 pre-split buffers (uint2 = {hi, lo})
__device__ uint2 g_Bsp [NQKV_ * D_];       // biggest weight: w_qkv (reused for all B)
__device__ uint2 g_Ahid[S_ * D_];          // hidden (QKV + gates A)
__device__ uint2 g_Amid[S_ * D_];          // mid (W_o A)
__device__ uint2 g_Acin[KVH_ * NC_ * CDIM_]; // ckin / cvin
__device__ uint2 g_Ah1 [KVH_ * NC_ * CDIM_]; // h1

// ---------------- helpers ----------------
__device__ __forceinline__ unsigned f2tf(float x) {
    unsigned r;
    asm("cvt.rna.tf32.f32 %0, %1;" : "=r"(r) : "f"(x));
    return r;
}

__device__ __forceinline__ void mma_tf32(float c[4], unsigned a0, unsigned a1,
                                         unsigned a2, unsigned a3,
                                         unsigned b0, unsigned b1) {
    asm volatile(
        "mma.sync.aligned.m16n8k8.row.col.f32.tf32.tf32.f32 "
        "{%0,%1,%2,%3}, {%4,%5,%6,%7}, {%8,%9}, {%0,%1,%2,%3};\n"
        : "+f"(c[0]), "+f"(c[1]), "+f"(c[2]), "+f"(c[3])
        : "r"(a0), "r"(a1), "r"(a2), "r"(a3), "r"(b0), "r"(b1));
}

__device__ __forceinline__ void cp16(unsigned dst, const void* src, int zfill) {
    asm volatile("cp.async.ca.shared.global [%0], [%1], 16, %2;\n"
                 :: "r"(dst), "l"(src), "r"(zfill));
}

// ---------------- hi/lo split pre-pass (2 floats/thread, 16B store) ----------
__global__ void split_kernel(const float* __restrict__ src,
                             uint4* __restrict__ dst, int n2) {
    int i = blockIdx.x * blockDim.x + threadIdx.x;
    if (i >= n2) return;
    float2 v = ((const float2*)src)[i];
    unsigned h0 = f2tf(v.x);
    unsigned l0 = f2tf(v.x - __uint_as_float(h0));
    unsigned h1 = f2tf(v.y);
    unsigned l1 = f2tf(v.y - __uint_as_float(h1));
    dst[i] = make_uint4(h0, l0, h1, l1);
}

// =================== TF32 GEMM v2: pre-split hi/lo operands ===================
// C[M,N] = A[M,K] @ B[N,K]^T (3xTF32). Tile 128x64x16, 256 thr, 2 CTA/SM.
// A,B are uint2{hi,lo}. blockIdx.x = M-block (fast), .y = N-block, .z = split-K.
#define V2_BM 128
#define V2_BN 64
#define V2_BK 16
#define V2_AST 20                    // uint2 row stride (pad: 40 words = 8 mod 32 banks)
#define V2_ASTAGE (128 * V2_AST)     // uint2 per A stage
#define V2_BSTAGE (64 * V2_AST)
#define V2_SMEM_BYTES ((2 * (V2_ASTAGE + V2_BSTAGE)) * 8)   // 61440

template <int ACT, bool NGUARD>
__global__ void __launch_bounds__(256, 2)
gemm_v2(const uint2* __restrict__ A, const uint2* __restrict__ B,
        const float* __restrict__ bias, float* __restrict__ C,
        int M, int N, int K, int klen) {
    extern __shared__ uint2 sm[];
    uint2* As = sm;
    uint2* Bs = sm + 2 * V2_ASTAGE;

    const int tid = threadIdx.x;
    const int wid = tid >> 5, lane = tid & 31;
    const int warp_m = wid & 3;          // 4 slabs x 32 rows
    const int warp_n = wid >> 2;         // 2 slabs x 32 cols
    const int g = lane >> 2, tg = lane & 3;
    const int bm = blockIdx.x * V2_BM, bn = blockIdx.y * V2_BN;
    const int kglob = blockIdx.z * klen;

    // loaders: A 2 thr/row x 4 chunks; B 4 thr/row x 2 chunks (16B chunks,
    // each chunk = 2 uint2; dst stride per chunk = 16B to stay contiguous)
    const int alr = tid >> 1, alc = (tid & 1) * 8;     // uint2 col base
    const int blr = tid >> 2, blc = (tid & 3) * 4;

    int brow = bn + blr;
    int browc = NGUARD ? (brow < N ? brow : N - 1) : brow;
    const int bzf = (!NGUARD || brow < N) ? 16 : 0;

    const uint2* Ab = A + (size_t)(bm + alr) * K + kglob + alc;
    const uint2* Bb = B + (size_t)browc * K + kglob + blc;
    const unsigned sa = (unsigned)__cvta_generic_to_shared(As) +
                        (unsigned)(alr * V2_AST + alc) * 8u;
    const unsigned sb = (unsigned)__cvta_generic_to_shared(Bs) +
                        (unsigned)(blr * V2_AST + blc) * 8u;

    float acc[2][4][4];
#pragma unroll
    for (int i = 0; i < 2; i++)
#pragma unroll
        for (int j = 0; j < 4; j++)
#pragma unroll
            for (int e = 0; e < 4; e++) acc[i][j][e] = 0.f;

    const int ntiles = klen / V2_BK;

#define V2LOAD(stg, t)                                                       \
    do {                                                                     \
        const uint2* ap = Ab + (t) * V2_BK;                                  \
        const uint2* bp = Bb + (t) * V2_BK;                                  \
        unsigned ad = sa + (stg) * V2_ASTAGE * 8u;                           \
        unsigned bd = sb + (stg) * V2_BSTAGE * 8u;                           \
        _Pragma("unroll")                                                    \
        for (int u = 0; u < 4; u++) cp16(ad + u * 16u, ap + u * 2, 16);      \
        _Pragma("unroll")                                                    \
        for (int u = 0; u < 2; u++) cp16(bd + u * 16u, bp + u * 2, bzf);     \
        asm volatile("cp.async.commit_group;\n");                            \
    } while (0)

    V2LOAD(0, 0);

    for (int t = 0; t < ntiles; t++) {
        if (t + 1 < ntiles) {
            V2LOAD((t + 1) & 1, t + 1);
            asm volatile("cp.async.wait_group 1;\n");
        } else {
            asm volatile("cp.async.wait_group 0;\n");
        }
        __syncthreads();

        const uint2* as = As + (t & 1) * V2_ASTAGE;
        const uint2* bs = Bs + (t & 1) * V2_BSTAGE;
#pragma unroll
        for (int ks = 0; ks < 2; ks++) {
            const int cb = ks * 8;
            uint2 a[2][4];
#pragma unroll
            for (int mt = 0; mt < 2; mt++) {
                const int r0 = (warp_m * 32 + mt * 16 + g) * V2_AST;
                const int r1 = r0 + 8 * V2_AST;
                a[mt][0] = as[r0 + cb + tg];
                a[mt][1] = as[r1 + cb + tg];
                a[mt][2] = as[r0 + cb + tg + 4];
                a[mt][3] = as[r1 + cb + tg + 4];
            }
            uint2 b[4][2];
#pragma unroll
            for (int nt = 0; nt < 4; nt++) {
                const int rn = (warp_n * 32 + nt * 8 + g) * V2_AST;
                b[nt][0] = bs[rn + cb + tg];
                b[nt][1] = bs[rn + cb + tg + 4];
            }
#pragma unroll
            for (int mt = 0; mt < 2; mt++)
#pragma unroll
                for (int nt = 0; nt < 4; nt++) {
                    mma_tf32(acc[mt][nt], a[mt][0].y, a[mt][1].y, a[mt][2].y,
                             a[mt][3].y, b[nt][0].x, b[nt][1].x);
                    mma_tf32(acc[mt][nt], a[mt][0].x, a[mt][1].x, a[mt][2].x,
                             a[mt][3].x, b[nt][0].y, b[nt][1].y);
                    mma_tf32(acc[mt][nt], a[mt][0].x, a[mt][1].x, a[mt][2].x,
                             a[mt][3].x, b[nt][0].x, b[nt][1].x);
                }
        }
        __syncthreads();
    }
#undef V2LOAD

    const bool split = (gridDim.z > 1);
#pragma unroll
    for (int mt = 0; mt < 2; mt++) {
#pragma unroll
        for (int nt = 0; nt < 4; nt++) {
#pragma unroll
            for (int e = 0; e < 4; e++) {
                int row = bm + warp_m * 32 + mt * 16 + g + ((e >= 2) ? 8 : 0);
                int col = bn + warp_n * 32 + nt * 8 + 2 * tg + (e & 1);
                if (NGUARD && col >= N) continue;
                float v = acc[mt][nt][e];
                if (split) {
                    g_part[(size_t)blockIdx.z * M * N + (size_t)row * N + col] = v;
                } else {
                    if (bias) v += bias[col];
                    if (ACT == 1) v = fmaxf(v, 0.f);
                    C[(size_t)row * N + col] = v;
                }
            }
        }
    }
}

// split-K reduce: C = act(sum_z part + bias). ACT: 0 none, 2 sigmoid
template <int ACT>
__global__ void reduce_splitk(const float* __restrict__ bias,
                              float* __restrict__ C, int MN, int N, int splits) {
    int idx = blockIdx.x * blockDim.x + threadIdx.x;
    if (idx >= MN) return;
    float s = 0.f;
    for (int z = 0; z < splits; z++) s += g_part[(size_t)z * MN + idx];
    if (bias) s += bias[idx % N];
    if (ACT == 2) s = 1.f / (1.f + expf(-s));
    C[idx] = s;
}

// ---------------- build compressed MLP inputs --------------------------------
__global__ void build_cin_kernel(const float* __restrict__ k_pos,
                                 const float* __restrict__ v_pos) {
    int idx = blockIdx.x * blockDim.x + threadIdx.x;
    if (idx >= KVH_ * NC_ * CDIM_) return;
    int r = idx >> 11, col = idx & 2047;
    int h = r >> 6, c = r & 63;
    int t = col >> 7, d = col & 127;
    int s = c * CB_ + t;
    size_t base = (size_t)s * NQKV_ + h * DH_ + d;
    int pidx = (h * CB_ + t) * DH_ + d;
    g_ckin[idx] = g_qkv[base + 4096] + k_pos[pidx];
    g_cvin[idx] = g_qkv[base + 5120] + v_pos[pidx];
}

// ---------------- scatter compressed K/V (prepend mem token) -----------------
__global__ void scatter_c_kernel(const float* __restrict__ mem_kv) {
    int idx = blockIdx.x * blockDim.x + threadIdx.x;
    if (idx >= KVH_ * (NC_ + 1) * DH_) return;
    int d = idx & 127, jh = idx >> 7;
    int h = jh / (NC_ + 1), j = jh % (NC_ + 1);
    float kv, vv;
    if (j == 0) {
        kv = mem_kv[h * DH_ + d];
        vv = mem_kv[KVH_ * DH_ + h * DH_ + d];
    } else {
        int r = (h * NC_ + (j - 1)) * DH_ + d;
        kv = g_ckb[r];
        vv = g_cvb[r];
    }
    g_ck[idx] = kv;
    g_cv[idx] = vv;
}

// ---------------- RoPE (interleaved, theta=10000) ----------------------------
__global__ void rope_kernel() {
    int i = blockIdx.x;
    int y = blockIdx.y;
    int p = threadIdx.x;
    const float* src;
    float* dst;
    if (y < H_) {
        src = g_qkv + (size_t)i * NQKV_ + y * DH_;
        dst = g_rq + ((size_t)i * H_ + y) * DH_;
    } else {
        src = g_qkv + (size_t)i * NQKV_ + 4096 + (y - H_) * DH_;
        dst = g_rk + ((size_t)i * KVH_ + (y - H_)) * DH_;
    }
    float inv = (float)pow(10000.0, -(double)(2 * p) / 128.0);
    float ang = (float)i * inv;
    float sn, cs;
    sincosf(ang, &sn, &cs);
    float x0 = src[2 * p], x1 = src[2 * p + 1];
    dst[2 * p]     = x0 * cs - x1 * sn;
    dst[2 * p + 1] = x1 * cs + x0 * sn;
}

// ---------------- compressed attention + importance top-k --------------------
__global__ void comp_attn_kernel() {
    int i = blockIdx.x;
    int h = blockIdx.y;
    int tid = threadIdx.x;
    int g = tid >> 5, lane = tid & 31;
    __shared__ float sim[4][65];
    __shared__ float imp[64];

    const float* qp = g_qkv + (size_t)i * NQKV_ + (h * 4 + g) * DH_;
    float q0 = qp[lane], q1 = qp[lane + 32], q2 = qp[lane + 64], q3 = qp[lane + 96];

    for (int j = 0; j < 65; j++) {
        const float* kp = g_ck + (h * 65 + j) * DH_;
        float d = q0 * kp[lane] + q1 * kp[lane + 32] + q2 * kp[lane + 64] + q3 * kp[lane + 96];
#pragma unroll
        for (int o = 16; o > 0; o >>= 1) d += __shfl_down_sync(0xffffffffu, d, o);
        if (lane == 0) {
            bool vis = (j == 0) || (i >= j * CB_);
            sim[g][j] = vis ? d * SCALE_ : NEGF;
        }
    }
    __syncwarp();

    float m = NEGF;
    for (int j = lane; j < 65; j += 32) m = fmaxf(m, sim[g][j]);
#pragma unroll
    for (int o = 16; o > 0; o >>= 1) m = fmaxf(m, __shfl_xor_sync(0xffffffffu, m, o));
    float den = 0.f;
    for (int j = lane; j < 65; j += 32) den += expf(sim[g][j] - m);
#pragma unroll
    for (int o = 16; o > 0; o >>= 1) den += __shfl_xor_sync(0xffffffffu, den, o);
    float invden = 1.f / den;

    float o0 = 0, o1 = 0, o2 = 0, o3 = 0;
    for (int j = 0; j < 65; j++) {
        float p = expf(sim[g][j] - m) * invden;
        const float* vp = g_cv + (h * 65 + j) * DH_;
        o0 += p * vp[lane];
        o1 += p * vp[lane + 32];
        o2 += p * vp[lane + 64];
        o3 += p * vp[lane + 96];
    }
    float* op = g_cout + ((size_t)i * H_ + h * 4 + g) * DH_;
    op[lane] = o0; op[lane + 32] = o1; op[lane + 64] = o2; op[lane + 96] = o3;

    __syncthreads();

    if (tid < 64) {
        float s = sim[0][tid + 1] + sim[1][tid + 1] + sim[2][tid + 1] + sim[3][tid + 1];
        imp[tid] = 0.25f * s;
    }
    __syncthreads();

    if (tid == 0) {
        float mm = -1000.f;
        for (int j = 0; j < 64; j++) mm = fmaxf(mm, imp[j]);
        float dd = expf(-1000.f - mm);
        for (int j = 0; j < 64; j++) dd += expf(imp[j] - mm);
        float inv = 1.f / dd;
        unsigned long long used = 0ull;
        int* sp = g_sel + (h * S_ + i) * 5;
        int* okp = g_selok + (h * S_ + i) * 4;
        for (int r = 0; r < NSEL_; r++) {
            float bp = -1.f;
            int bj = 0;
            for (int j = 0; j < 64; j++) {
                if ((used >> j) & 1ull) continue;
                float p = expf(imp[j] - mm) * inv;
                if (p > bp) { bp = p; bj = j; }
            }
            used |= 1ull << bj;
            sp[r] = bj;
            okp[r] = (bp > 1e-10f) ? 1 : 0;
        }
        sp[4] = i >> 4;
    }
}

// ---------------- fine (selected-block) attention ----------------------------
__global__ void fine_attn_kernel() {
    int i = blockIdx.x, qh = blockIdx.y;
    int h = qh >> 2;
    int tid = threadIdx.x;
    int w = tid >> 5, lane = tid & 31;
    __shared__ float sim[80];
    __shared__ int sblk[5];
    __shared__ int sok[4];
    __shared__ float ssoft[2];

    if (tid < 5) sblk[tid] = g_sel[(h * S_ + i) * 5 + tid];
    if (tid < 4) sok[tid] = g_selok[(h * S_ + i) * 4 + tid];
    __syncthreads();

    const float* qp = g_rq + ((size_t)i * H_ + qh) * DH_;
    float q0 = qp[lane], q1 = qp[lane + 32], q2 = qp[lane + 64], q3 = qp[lane + 96];

    for (int j = w * 20; j < w * 20 + 20; j++) {
        int r = j >> 4, t = j & 15;
        int skey = sblk[r] * SB_ + t;
        const float* kp = g_rk + ((size_t)skey * KVH_ + h) * DH_;
        float d = q0 * kp[lane] + q1 * kp[lane + 32] + q2 * kp[lane + 64] + q3 * kp[lane + 96];
#pragma unroll
        for (int o = 16; o > 0; o >>= 1) d += __shfl_down_sync(0xffffffffu, d, o);
        if (lane == 0) {
            bool vis = (r < 4) ? (sok[r] != 0) : (t <= (i & 15));
            sim[j] = vis ? d * SCALE_ : NEGF;
        }
    }
    __syncthreads();

    if (tid == 0) {
        float m = NEGF;
        for (int j = 0; j < 80; j++) m = fmaxf(m, sim[j]);
        float dd = 0.f;
        for (int j = 0; j < 80; j++) dd += expf(sim[j] - m);
        ssoft[0] = m;
        ssoft[1] = 1.f / dd;
    }
    __syncthreads();
    if (tid < 80) sim[tid] = expf(sim[tid] - ssoft[0]) * ssoft[1];
    __syncthreads();

    float acc = 0.f;
    int d = tid;
    for (int j = 0; j < 80; j++) {
        int r = j >> 4, t = j & 15;
        int skey = sblk[r] * SB_ + t;
        acc += sim[j] * g_qkv[(size_t)skey * NQKV_ + 5120 + h * DH_ + d];
    }
    g_fout[((size_t)i * H_ + qh) * DH_ + d] = acc;
}

// ---------------- sliding-window attention (65 keys, clipped) ----------------
__global__ void slide_attn_kernel() {
    int i = blockIdx.x, qh = blockIdx.y;
    int h = qh >> 2;
    int tid = threadIdx.x;
    int w = tid >> 5, lane = tid & 31;
    __shared__ float sim[65];
    __shared__ float ssoft[2];

    int j0 = i - WIN_;
    if (j0 < 0) j0 = 0;
    int nj = i - j0 + 1;

    const float* qp = g_rq + ((size_t)i * H_ + qh) * DH_;
    float q0 = qp[lane], q1 = qp[lane + 32], q2 = qp[lane + 64], q3 = qp[lane + 96];

    for (int j = w; j < nj; j += 4) {
        int s = j0 + j;
        const float* kp = g_rk + ((size_t)s * KVH_ + h) * DH_;
        float d = q0 * kp[lane] + q1 * kp[lane + 32] + q2 * kp[lane + 64] + q3 * kp[lane + 96];
#pragma unroll
        for (int o = 16; o > 0; o >>= 1) d += __shfl_down_sync(0xffffffffu, d, o);
        if (lane == 0) sim[j] = d * SCALE_;
    }
    __syncthreads();

    if (tid == 0) {
        float m = NEGF;
        for (int j = 0; j < nj; j++) m = fmaxf(m, sim[j]);
        float dd = 0.f;
        for (int j = 0; j < nj; j++) dd += expf(sim[j] - m);
        ssoft[0] = m;
        ssoft[1] = 1.f / dd;
    }
    __syncthreads();
    if (tid < nj) sim[tid] = expf(sim[tid] - ssoft[0]) * ssoft[1];
    __syncthreads();

    float acc = 0.f;
    int d = tid;
    for (int j = 0; j < nj; j++)
        acc += sim[j] * g_qkv[(size_t)(j0 + j) * NQKV_ + 5120 + h * DH_ + d];
    g_sout[((size_t)i * H_ + qh) * DH_ + d] = acc;
}

// ---------------- gate-combine ------------------------------------------------
__global__ void combine_kernel() {
    int idx = blockIdx.x * blockDim.x + threadIdx.x;
    if (idx >= S_ * D_) return;
    int i = idx >> 12, hd = idx & 4095, hh = hd >> 7;
    const float* gp = g_gates + i * 96 + hh * 3;
    g_mid[idx] = gp[0] * g_cout[idx] + gp[1] * g_fout[idx] + gp[2] * g_sout[idx];
}

// ---------------- launch ------------------------------------------------------
static inline void run_split(const float* src, void* dst, int n) {
    int n2 = n / 2;
    split_kernel<<<(n2 + 255) / 256, 256>>>(src, (uint4*)dst, n2);
}

extern "C" void kernel_launch(void* const* d_in, const int* in_sizes, int n_in,
                              void* d_out, int out_size) {
    const float* hidden = (const float*)d_in[0];
    const float* w_qkv  = (const float*)d_in[1];
    const float* w_o    = (const float*)d_in[2];
    const float* k_pos  = (const float*)d_in[3];
    const float* v_pos  = (const float*)d_in[4];
    const float* k_w1   = (const float*)d_in[5];
    const float* k_b1   = (const float*)d_in[6];
    const float* k_w2   = (const float*)d_in[7];
    const float* k_b2   = (const float*)d_in[8];
    const float* v_w1   = (const float*)d_in[9];
    const float* v_b1   = (const float*)d_in[10];
    const float* v_w2   = (const float*)d_in[11];
    const float* v_b2   = (const float*)d_in[12];
    const float* mem_kv = (const float*)d_in[13];
    const float* w_gate = (const float*)d_in[14];
    const float* b_gate = (const float*)d_in[15];
    float* out = (float*)d_out;

    float *qkv, *ckin, *cvin, *h1, *ckb, *cvb, *gates, *mid;
    void *Bsp, *Ahid, *Amid, *Acin, *Ah1;
    cudaGetSymbolAddress((void**)&qkv,   g_qkv);
    cudaGetSymbolAddress((void**)&ckin,  g_ckin);
    cudaGetSymbolAddress((void**)&cvin,  g_cvin);
    cudaGetSymbolAddress((void**)&h1,    g_h1);
    cudaGetSymbolAddress((void**)&ckb,   g_ckb);
    cudaGetSymbolAddress((void**)&cvb,   g_cvb);
    cudaGetSymbolAddress((void**)&gates, g_gates);
    cudaGetSymbolAddress((void**)&mid,   g_mid);
    cudaGetSymbolAddress(&Bsp,  g_Bsp);
    cudaGetSymbolAddress(&Ahid, g_Ahid);
    cudaGetSymbolAddress(&Amid, g_Amid);
    cudaGetSymbolAddress(&Acin, g_Acin);
    cudaGetSymbolAddress(&Ah1,  g_Ah1);

    cudaFuncSetAttribute(gemm_v2<0, false>,
                         cudaFuncAttributeMaxDynamicSharedMemorySize, V2_SMEM_BYTES);
    cudaFuncSetAttribute(gemm_v2<1, false>,
                         cudaFuncAttributeMaxDynamicSharedMemorySize, V2_SMEM_BYTES);
    cudaFuncSetAttribute(gemm_v2<0, true>,
                         cudaFuncAttributeMaxDynamicSharedMemorySize, V2_SMEM_BYTES);

    // 1. QKV projection (1024 x 6144 x 4096)
    run_split(hidden, Ahid, S_ * D_);
    run_split(w_qkv, Bsp, NQKV_ * D_);
    gemm_v2<0, false><<<dim3(S_ / V2_BM, NQKV_ / V2_BN, 1), 256, V2_SMEM_BYTES>>>(
        (const uint2*)Ahid, (const uint2*)Bsp, nullptr, qkv, S_, NQKV_, D_, D_);

    // 2. compressed MLP inputs
    build_cin_kernel<<<(KVH_ * NC_ * CDIM_ + 255) / 256, 256>>>(k_pos, v_pos);

    // 3. K compress MLP
    run_split(ckin, Acin, 512 * CDIM_);
    run_split(k_w1, Bsp, CDIM_ * CDIM_);
    gemm_v2<1, false><<<dim3(4, CDIM_ / V2_BN, 1), 256, V2_SMEM_BYTES>>>(
        (const uint2*)Acin, (const uint2*)Bsp, k_b1, h1, 512, CDIM_, CDIM_, CDIM_);
    run_split(h1, Ah1, 512 * CDIM_);
    run_split(k_w2, Bsp, DH_ * CDIM_);
    gemm_v2<0, false><<<dim3(4, 2, 16), 256, V2_SMEM_BYTES>>>(
        (const uint2*)Ah1, (const uint2*)Bsp, nullptr, ckb, 512, DH_, CDIM_, CDIM_ / 16);
    reduce_splitk<0><<<(512 * DH_ + 255) / 256, 256>>>(k_b2, ckb, 512 * DH_, DH_, 16);

    // 4. V compress MLP
    run_split(cvin, Acin, 512 * CDIM_);
    run_split(v_w1, Bsp, CDIM_ * CDIM_);
    gemm_v2<1, false><<<dim3(4, CDIM_ / V2_BN, 1), 256, V2_SMEM_BYTES>>>(
        (const uint2*)Acin, (const uint2*)Bsp, v_b1, h1, 512, CDIM_, CDIM_, CDIM_);
    run_split(h1, Ah1, 512 * CDIM_);
    run_split(v_w2, Bsp, DH_ * CDIM_);
    gemm_v2<0, false><<<dim3(4, 2, 16), 256, V2_SMEM_BYTES>>>(
        (const uint2*)Ah1, (const uint2*)Bsp, nullptr, cvb, 512, DH_, CDIM_, CDIM_ / 16);
    reduce_splitk<0><<<(512 * DH_ + 255) / 256, 256>>>(v_b2, cvb, 512 * DH_, DH_, 16);

    // 5. prepend mem token
    scatter_c_kernel<<<(KVH_ * (NC_ + 1) * DH_ + 255) / 256, 256>>>(mem_kv);
    // 6. RoPE
    rope_kernel<<<dim3(S_, H_ + KVH_), 64>>>();
    // 7. compressed attention + selection
    comp_attn_kernel<<<dim3(S_, KVH_), 128>>>();
    // 8. fine attention
    fine_attn_kernel<<<dim3(S_, H_), 128>>>();
    // 9. sliding window attention
    slide_attn_kernel<<<dim3(S_, H_), 128>>>();

    // 10. gates (1024 x 96 x 4096) split-K=16 + sigmoid in reduce
    run_split(w_gate, Bsp, 96 * D_);
    gemm_v2<0, true><<<dim3(S_ / V2_BM, 2, 16), 256, V2_SMEM_BYTES>>>(
        (const uint2*)Ahid, (const uint2*)Bsp, nullptr, gates, S_, 96, D_, D_ / 16);
    reduce_splitk<2><<<(S_ * 96 + 255) / 256, 256>>>(b_gate, gates, S_ * 96, 96, 16);

    // 11. combine
    combine_kernel<<<(S_ * D_ + 255) / 256, 256>>>();

    // 12. output projection (1024 x 4096 x 4096)
    run_split(mid, Amid, S_ * D_);
    run_split(w_o, Bsp, D_ * D_);
    gemm_v2<0, false><<<dim3(S_ / V2_BM, D_ / V2_BN, 1), 256, V2_SMEM_BYTES>>>(
        (const uint2*)Amid, (const uint2*)Bsp, nullptr, out, S_, D_, D_, D_);
}

// round 10
// speedup vs baseline: 1.1363x; 1.1363x over previous
#include <cuda_runtime.h>
#include <cuda_bf16.h>
#include <math.h>

// ---------------- problem constants ----------------
#define S_   1024
#define H_   32
#define KVH_ 8
#define DH_  128
#define D_   4096
#define CB_  16
#define NC_  64        // S/CB
#define SB_  16
#define NSEL_ 4
#define WIN_ 64
#define NQKV_ 6144     // H*DH + 2*KVH*DH
#define CDIM_ 2048     // CB*DH
#define NEGF (-3.402823466e38f)
#define SCALE_ 0.08838834764831844056f  // 128^-0.5

// ---------------- scratch (no allocs allowed) ----------------
__device__ float g_qkv [S_ * NQKV_];
__device__ float g_rq  [S_ * H_ * DH_];
__device__ float g_rk  [S_ * KVH_ * DH_];
__device__ float g_ckin[KVH_ * NC_ * CDIM_];
__device__ float g_cvin[KVH_ * NC_ * CDIM_];
__device__ float g_h1  [KVH_ * NC_ * CDIM_];
__device__ float g_ckb [KVH_ * NC_ * DH_];
__device__ float g_cvb [KVH_ * NC_ * DH_];
__device__ float g_ck  [KVH_ * (NC_ + 1) * DH_];
__device__ float g_cv  [KVH_ * (NC_ + 1) * DH_];
__device__ float g_cout[S_ * H_ * DH_];
__device__ float g_fout[S_ * H_ * DH_];
__device__ float g_sout[S_ * H_ * DH_];
__device__ int   g_sel [KVH_ * S_ * 5];
__device__ int   g_selok[KVH_ * S_ * 4];
__device__ float g_gates[S_ * 96];
__device__ float g_mid [S_ * D_];
__device__ float g_part[16 * 1024 * 96];   // split-K partials (max: gates)

// ---------------- helpers ----------------
__device__ __forceinline__ unsigned f2tf(float x) {
    unsigned r;
    asm("cvt.rna.tf32.f32 %0, %1;" : "=r"(r) : "f"(x));
    return r;
}

__device__ __forceinline__ void mma_tf32(float c[4], unsigned a0, unsigned a1,
                                         unsigned a2, unsigned a3,
                                         unsigned b0, unsigned b1) {
    asm volatile(
        "mma.sync.aligned.m16n8k8.row.col.f32.tf32.tf32.f32 "
        "{%0,%1,%2,%3}, {%4,%5,%6,%7}, {%8,%9}, {%0,%1,%2,%3};\n"
        : "+f"(c[0]), "+f"(c[1]), "+f"(c[2]), "+f"(c[3])
        : "r"(a0), "r"(a1), "r"(a2), "r"(a3), "r"(b0), "r"(b1));
}

__device__ __forceinline__ void cp16(unsigned dst, const void* src, int zfill) {
    asm volatile("cp.async.ca.shared.global [%0], [%1], 16, %2;\n"
                 :: "r"(dst), "l"(src), "r"(zfill));
}

// ============ TF32 GEMM v3: in-kernel hi/lo split, 512 threads ==============
// C[M,N] = A[M,K] @ B[N,K]^T (3xTF32, fp32-accurate).
// Tile 128x128x32, 512 threads, warp tile 32x32 (4x4 warps) -> 32 acc regs,
// 16 warps/SM. fp32 smem (no extra global traffic), stride 36 (4 mod 32:
// fragment LDS banks 4g+tg — conflict-free). Double-buffered cp.async.
// blockIdx.x = M-block (fast, shares B panel), .y = N-block, .z = split-K.
#define V3_ST 36
#define V3_STAGE (128 * V3_ST)                  // floats per matrix per stage
#define V3_SMEM_BYTES (4 * V3_STAGE * 4)        // 73728

template <int ACT, bool NGUARD>
__global__ void __launch_bounds__(512, 1)
gemm_v3(const float* __restrict__ A, const float* __restrict__ B,
        const float* __restrict__ bias, float* __restrict__ C,
        int M, int N, int K, int klen) {
    extern __shared__ float sm[];
    float* As = sm;                     // [2][128*36]
    float* Bs = sm + 2 * V3_STAGE;

    const int tid = threadIdx.x;
    const int wid = tid >> 5, lane = tid & 31;
    const int warp_m = wid & 3;         // 4 x 32 rows
    const int warp_n = wid >> 2;        // 4 x 32 cols
    const int g = lane >> 2, tg = lane & 3;
    const int bm = blockIdx.x * 128, bn = blockIdx.y * 128;
    const int kglob = blockIdx.z * klen;

    // loaders: 4 threads/row, 8 floats (2 x 16B) each; 128 rows covered
    const int arow = tid >> 2, acol = (tid & 3) * 8;
    int brow = bn + arow;
    int browc = NGUARD ? (brow < N ? brow : N - 1) : brow;
    const int bzf = (!NGUARD || brow < N) ? 16 : 0;

    const float* Ab = A + (size_t)(bm + arow) * K + kglob + acol;
    const float* Bb = B + (size_t)browc * K + kglob + acol;
    const unsigned sa = (unsigned)__cvta_generic_to_shared(As) +
                        (unsigned)(arow * V3_ST + acol) * 4u;
    const unsigned sb = (unsigned)__cvta_generic_to_shared(Bs) +
                        (unsigned)(arow * V3_ST + acol) * 4u;

    float acc[2][4][4];
#pragma unroll
    for (int i = 0; i < 2; i++)
#pragma unroll
        for (int j = 0; j < 4; j++)
#pragma unroll
            for (int e = 0; e < 4; e++) acc[i][j][e] = 0.f;

    const int ntiles = klen / 32;

#define V3LOAD(stg, t)                                                       \
    do {                                                                     \
        const float* ap = Ab + (t) * 32;                                     \
        const float* bp = Bb + (t) * 32;                                     \
        unsigned ad = sa + (stg) * V3_STAGE * 4u;                            \
        unsigned bd = sb + (stg) * V3_STAGE * 4u;                            \
        cp16(ad, ap, 16);       cp16(ad + 16u, ap + 4, 16);                  \
        cp16(bd, bp, bzf);      cp16(bd + 16u, bp + 4, bzf);                 \
        asm volatile("cp.async.commit_group;\n");                            \
    } while (0)

    V3LOAD(0, 0);

    for (int t = 0; t < ntiles; t++) {
        if (t + 1 < ntiles) {
            V3LOAD((t + 1) & 1, t + 1);
            asm volatile("cp.async.wait_group 1;\n");
        } else {
            asm volatile("cp.async.wait_group 0;\n");
        }
        __syncthreads();

        const float* as = As + (t & 1) * V3_STAGE;
        const float* bs = Bs + (t & 1) * V3_STAGE;
#pragma unroll
        for (int ks = 0; ks < 4; ks++) {
            const int cb = ks * 8;
            unsigned ah[2][4], al[2][4];
#pragma unroll
            for (int mt = 0; mt < 2; mt++) {
                const int r0 = (warp_m * 32 + mt * 16 + g) * V3_ST;
                const int r1 = r0 + 8 * V3_ST;
                float x0 = as[r0 + cb + tg];
                float x1 = as[r1 + cb + tg];
                float x2 = as[r0 + cb + tg + 4];
                float x3 = as[r1 + cb + tg + 4];
                ah[mt][0] = f2tf(x0); al[mt][0] = f2tf(x0 - __uint_as_float(ah[mt][0]));
                ah[mt][1] = f2tf(x1); al[mt][1] = f2tf(x1 - __uint_as_float(ah[mt][1]));
                ah[mt][2] = f2tf(x2); al[mt][2] = f2tf(x2 - __uint_as_float(ah[mt][2]));
                ah[mt][3] = f2tf(x3); al[mt][3] = f2tf(x3 - __uint_as_float(ah[mt][3]));
            }
            unsigned bh[4][2], bl[4][2];
#pragma unroll
            for (int nt = 0; nt < 4; nt++) {
                const int rn = (warp_n * 32 + nt * 8 + g) * V3_ST;
                float y0 = bs[rn + cb + tg];
                float y1 = bs[rn + cb + tg + 4];
                bh[nt][0] = f2tf(y0); bl[nt][0] = f2tf(y0 - __uint_as_float(bh[nt][0]));
                bh[nt][1] = f2tf(y1); bl[nt][1] = f2tf(y1 - __uint_as_float(bh[nt][1]));
            }
#pragma unroll
            for (int mt = 0; mt < 2; mt++)
#pragma unroll
                for (int nt = 0; nt < 4; nt++) {
                    mma_tf32(acc[mt][nt], al[mt][0], al[mt][1], al[mt][2],
                             al[mt][3], bh[nt][0], bh[nt][1]);
                    mma_tf32(acc[mt][nt], ah[mt][0], ah[mt][1], ah[mt][2],
                             ah[mt][3], bl[nt][0], bl[nt][1]);
                    mma_tf32(acc[mt][nt], ah[mt][0], ah[mt][1], ah[mt][2],
                             ah[mt][3], bh[nt][0], bh[nt][1]);
                }
        }
        __syncthreads();
    }
#undef V3LOAD

    const bool split = (gridDim.z > 1);
#pragma unroll
    for (int mt = 0; mt < 2; mt++) {
#pragma unroll
        for (int nt = 0; nt < 4; nt++) {
#pragma unroll
            for (int e = 0; e < 4; e++) {
                int row = bm + warp_m * 32 + mt * 16 + g + ((e >= 2) ? 8 : 0);
                int col = bn + warp_n * 32 + nt * 8 + 2 * tg + (e & 1);
                if (NGUARD && col >= N) continue;
                float v = acc[mt][nt][e];
                if (split) {
                    g_part[(size_t)blockIdx.z * M * N + (size_t)row * N + col] = v;
                } else {
                    if (bias) v += bias[col];
                    if (ACT == 1) v = fmaxf(v, 0.f);
                    C[(size_t)row * N + col] = v;
                }
            }
        }
    }
}

// split-K reduce: C = act(sum_z part + bias). ACT: 0 none, 2 sigmoid
template <int ACT>
__global__ void reduce_splitk(const float* __restrict__ bias,
                              float* __restrict__ C, int MN, int N, int splits) {
    int idx = blockIdx.x * blockDim.x + threadIdx.x;
    if (idx >= MN) return;
    float s = 0.f;
    for (int z = 0; z < splits; z++) s += g_part[(size_t)z * MN + idx];
    if (bias) s += bias[idx % N];
    if (ACT == 2) s = 1.f / (1.f + expf(-s));
    C[idx] = s;
}

// ---------------- build compressed MLP inputs --------------------------------
__global__ void build_cin_kernel(const float* __restrict__ k_pos,
                                 const float* __restrict__ v_pos) {
    int idx = blockIdx.x * blockDim.x + threadIdx.x;
    if (idx >= KVH_ * NC_ * CDIM_) return;
    int r = idx >> 11, col = idx & 2047;
    int h = r >> 6, c = r & 63;
    int t = col >> 7, d = col & 127;
    int s = c * CB_ + t;
    size_t base = (size_t)s * NQKV_ + h * DH_ + d;
    int pidx = (h * CB_ + t) * DH_ + d;
    g_ckin[idx] = g_qkv[base + 4096] + k_pos[pidx];
    g_cvin[idx] = g_qkv[base + 5120] + v_pos[pidx];
}

// ---------------- scatter compressed K/V (prepend mem token) -----------------
__global__ void scatter_c_kernel(const float* __restrict__ mem_kv) {
    int idx = blockIdx.x * blockDim.x + threadIdx.x;
    if (idx >= KVH_ * (NC_ + 1) * DH_) return;
    int d = idx & 127, jh = idx >> 7;
    int h = jh / (NC_ + 1), j = jh % (NC_ + 1);
    float kv, vv;
    if (j == 0) {
        kv = mem_kv[h * DH_ + d];
        vv = mem_kv[KVH_ * DH_ + h * DH_ + d];
    } else {
        int r = (h * NC_ + (j - 1)) * DH_ + d;
        kv = g_ckb[r];
        vv = g_cvb[r];
    }
    g_ck[idx] = kv;
    g_cv[idx] = vv;
}

// ---------------- RoPE (interleaved, theta=10000) ----------------------------
__global__ void rope_kernel() {
    int i = blockIdx.x;
    int y = blockIdx.y;
    int p = threadIdx.x;
    const float* src;
    float* dst;
    if (y < H_) {
        src = g_qkv + (size_t)i * NQKV_ + y * DH_;
        dst = g_rq + ((size_t)i * H_ + y) * DH_;
    } else {
        src = g_qkv + (size_t)i * NQKV_ + 4096 + (y - H_) * DH_;
        dst = g_rk + ((size_t)i * KVH_ + (y - H_)) * DH_;
    }
    float inv = (float)pow(10000.0, -(double)(2 * p) / 128.0);
    float ang = (float)i * inv;
    float sn, cs;
    sincosf(ang, &sn, &cs);
    float x0 = src[2 * p], x1 = src[2 * p + 1];
    dst[2 * p]     = x0 * cs - x1 * sn;
    dst[2 * p + 1] = x1 * cs + x0 * sn;
}

// ---------------- compressed attention + importance top-k --------------------
__global__ void comp_attn_kernel() {
    int i = blockIdx.x;
    int h = blockIdx.y;
    int tid = threadIdx.x;
    int g = tid >> 5, lane = tid & 31;
    __shared__ float sim[4][65];
    __shared__ float imp[64];

    const float* qp = g_qkv + (size_t)i * NQKV_ + (h * 4 + g) * DH_;
    float q0 = qp[lane], q1 = qp[lane + 32], q2 = qp[lane + 64], q3 = qp[lane + 96];

    for (int j = 0; j < 65; j++) {
        const float* kp = g_ck + (h * 65 + j) * DH_;
        float d = q0 * kp[lane] + q1 * kp[lane + 32] + q2 * kp[lane + 64] + q3 * kp[lane + 96];
#pragma unroll
        for (int o = 16; o > 0; o >>= 1) d += __shfl_down_sync(0xffffffffu, d, o);
        if (lane == 0) {
            bool vis = (j == 0) || (i >= j * CB_);
            sim[g][j] = vis ? d * SCALE_ : NEGF;
        }
    }
    __syncwarp();

    float m = NEGF;
    for (int j = lane; j < 65; j += 32) m = fmaxf(m, sim[g][j]);
#pragma unroll
    for (int o = 16; o > 0; o >>= 1) m = fmaxf(m, __shfl_xor_sync(0xffffffffu, m, o));
    float den = 0.f;
    for (int j = lane; j < 65; j += 32) den += expf(sim[g][j] - m);
#pragma unroll
    for (int o = 16; o > 0; o >>= 1) den += __shfl_xor_sync(0xffffffffu, den, o);
    float invden = 1.f / den;

    float o0 = 0, o1 = 0, o2 = 0, o3 = 0;
    for (int j = 0; j < 65; j++) {
        float p = expf(sim[g][j] - m) * invden;
        const float* vp = g_cv + (h * 65 + j) * DH_;
        o0 += p * vp[lane];
        o1 += p * vp[lane + 32];
        o2 += p * vp[lane + 64];
        o3 += p * vp[lane + 96];
    }
    float* op = g_cout + ((size_t)i * H_ + h * 4 + g) * DH_;
    op[lane] = o0; op[lane + 32] = o1; op[lane + 64] = o2; op[lane + 96] = o3;

    __syncthreads();

    if (tid < 64) {
        float s = sim[0][tid + 1] + sim[1][tid + 1] + sim[2][tid + 1] + sim[3][tid + 1];
        imp[tid] = 0.25f * s;
    }
    __syncthreads();

    if (tid == 0) {
        float mm = -1000.f;
        for (int j = 0; j < 64; j++) mm = fmaxf(mm, imp[j]);
        float dd = expf(-1000.f - mm);
        for (int j = 0; j < 64; j++) dd += expf(imp[j] - mm);
        float inv = 1.f / dd;
        unsigned long long used = 0ull;
        int* sp = g_sel + (h * S_ + i) * 5;
        int* okp = g_selok + (h * S_ + i) * 4;
        for (int r = 0; r < NSEL_; r++) {
            float bp = -1.f;
            int bj = 0;
            for (int j = 0; j < 64; j++) {
                if ((used >> j) & 1ull) continue;
                float p = expf(imp[j] - mm) * inv;
                if (p > bp) { bp = p; bj = j; }
            }
            used |= 1ull << bj;
            sp[r] = bj;
            okp[r] = (bp > 1e-10f) ? 1 : 0;
        }
        sp[4] = i >> 4;
    }
}

// ---------------- fine (selected-block) attention ----------------------------
__global__ void fine_attn_kernel() {
    int i = blockIdx.x, qh = blockIdx.y;
    int h = qh >> 2;
    int tid = threadIdx.x;
    int w = tid >> 5, lane = tid & 31;
    __shared__ float sim[80];
    __shared__ int sblk[5];
    __shared__ int sok[4];
    __shared__ float ssoft[2];

    if (tid < 5) sblk[tid] = g_sel[(h * S_ + i) * 5 + tid];
    if (tid < 4) sok[tid] = g_selok[(h * S_ + i) * 4 + tid];
    __syncthreads();

    const float* qp = g_rq + ((size_t)i * H_ + qh) * DH_;
    float q0 = qp[lane], q1 = qp[lane + 32], q2 = qp[lane + 64], q3 = qp[lane + 96];

    for (int j = w * 20; j < w * 20 + 20; j++) {
        int r = j >> 4, t = j & 15;
        int skey = sblk[r] * SB_ + t;
        const float* kp = g_rk + ((size_t)skey * KVH_ + h) * DH_;
        float d = q0 * kp[lane] + q1 * kp[lane + 32] + q2 * kp[lane + 64] + q3 * kp[lane + 96];
#pragma unroll
        for (int o = 16; o > 0; o >>= 1) d += __shfl_down_sync(0xffffffffu, d, o);
        if (lane == 0) {
            bool vis = (r < 4) ? (sok[r] != 0) : (t <= (i & 15));
            sim[j] = vis ? d * SCALE_ : NEGF;
        }
    }
    __syncthreads();

    if (tid == 0) {
        float m = NEGF;
        for (int j = 0; j < 80; j++) m = fmaxf(m, sim[j]);
        float dd = 0.f;
        for (int j = 0; j < 80; j++) dd += expf(sim[j] - m);
        ssoft[0] = m;
        ssoft[1] = 1.f / dd;
    }
    __syncthreads();
    if (tid < 80) sim[tid] = expf(sim[tid] - ssoft[0]) * ssoft[1];
    __syncthreads();

    float acc = 0.f;
    int d = tid;
    for (int j = 0; j < 80; j++) {
        int r = j >> 4, t = j & 15;
        int skey = sblk[r] * SB_ + t;
        acc += sim[j] * g_qkv[(size_t)skey * NQKV_ + 5120 + h * DH_ + d];
    }
    g_fout[((size_t)i * H_ + qh) * DH_ + d] = acc;
}

// ---------------- sliding-window attention (65 keys, clipped) ----------------
__global__ void slide_attn_kernel() {
    int i = blockIdx.x, qh = blockIdx.y;
    int h = qh >> 2;
    int tid = threadIdx.x;
    int w = tid >> 5, lane = tid & 31;
    __shared__ float sim[65];
    __shared__ float ssoft[2];

    int j0 = i - WIN_;
    if (j0 < 0) j0 = 0;
    int nj = i - j0 + 1;

    const float* qp = g_rq + ((size_t)i * H_ + qh) * DH_;
    float q0 = qp[lane], q1 = qp[lane + 32], q2 = qp[lane + 64], q3 = qp[lane + 96];

    for (int j = w; j < nj; j += 4) {
        int s = j0 + j;
        const float* kp = g_rk + ((size_t)s * KVH_ + h) * DH_;
        float d = q0 * kp[lane] + q1 * kp[lane + 32] + q2 * kp[lane + 64] + q3 * kp[lane + 96];
#pragma unroll
        for (int o = 16; o > 0; o >>= 1) d += __shfl_down_sync(0xffffffffu, d, o);
        if (lane == 0) sim[j] = d * SCALE_;
    }
    __syncthreads();

    if (tid == 0) {
        float m = NEGF;
        for (int j = 0; j < nj; j++) m = fmaxf(m, sim[j]);
        float dd = 0.f;
        for (int j = 0; j < nj; j++) dd += expf(sim[j] - m);
        ssoft[0] = m;
        ssoft[1] = 1.f / dd;
    }
    __syncthreads();
    if (tid < nj) sim[tid] = expf(sim[tid] - ssoft[0]) * ssoft[1];
    __syncthreads();

    float acc = 0.f;
    int d = tid;
    for (int j = 0; j < nj; j++)
        acc += sim[j] * g_qkv[(size_t)(j0 + j) * NQKV_ + 5120 + h * DH_ + d];
    g_sout[((size_t)i * H_ + qh) * DH_ + d] = acc;
}

// ---------------- gate-combine ------------------------------------------------
__global__ void combine_kernel() {
    int idx = blockIdx.x * blockDim.x + threadIdx.x;
    if (idx >= S_ * D_) return;
    int i = idx >> 12, hd = idx & 4095, hh = hd >> 7;
    const float* gp = g_gates + i * 96 + hh * 3;
    g_mid[idx] = gp[0] * g_cout[idx] + gp[1] * g_fout[idx] + gp[2] * g_sout[idx];
}

// ---------------- launch ------------------------------------------------------
extern "C" void kernel_launch(void* const* d_in, const int* in_sizes, int n_in,
                              void* d_out, int out_size) {
    const float* hidden = (const float*)d_in[0];
    const float* w_qkv  = (const float*)d_in[1];
    const float* w_o    = (const float*)d_in[2];
    const float* k_pos  = (const float*)d_in[3];
    const float* v_pos  = (const float*)d_in[4];
    const float* k_w1   = (const float*)d_in[5];
    const float* k_b1   = (const float*)d_in[6];
    const float* k_w2   = (const float*)d_in[7];
    const float* k_b2   = (const float*)d_in[8];
    const float* v_w1   = (const float*)d_in[9];
    const float* v_b1   = (const float*)d_in[10];
    const float* v_w2   = (const float*)d_in[11];
    const float* v_b2   = (const float*)d_in[12];
    const float* mem_kv = (const float*)d_in[13];
    const float* w_gate = (const float*)d_in[14];
    const float* b_gate = (const float*)d_in[15];
    float* out = (float*)d_out;

    float *qkv, *ckin, *cvin, *h1, *ckb, *cvb, *gates, *mid;
    cudaGetSymbolAddress((void**)&qkv,   g_qkv);
    cudaGetSymbolAddress((void**)&ckin,  g_ckin);
    cudaGetSymbolAddress((void**)&cvin,  g_cvin);
    cudaGetSymbolAddress((void**)&h1,    g_h1);
    cudaGetSymbolAddress((void**)&ckb,   g_ckb);
    cudaGetSymbolAddress((void**)&cvb,   g_cvb);
    cudaGetSymbolAddress((void**)&gates, g_gates);
    cudaGetSymbolAddress((void**)&mid,   g_mid);

    cudaFuncSetAttribute(gemm_v3<0, false>,
                         cudaFuncAttributeMaxDynamicSharedMemorySize, V3_SMEM_BYTES);
    cudaFuncSetAttribute(gemm_v3<1, false>,
                         cudaFuncAttributeMaxDynamicSharedMemorySize, V3_SMEM_BYTES);
    cudaFuncSetAttribute(gemm_v3<0, true>,
                         cudaFuncAttributeMaxDynamicSharedMemorySize, V3_SMEM_BYTES);

    // 1. QKV projection (1024 x 6144 x 4096)
    gemm_v3<0, false><<<dim3(S_ / 128, NQKV_ / 128, 1), 512, V3_SMEM_BYTES>>>(
        hidden, w_qkv, nullptr, qkv, S_, NQKV_, D_, D_);

    // 2. compressed MLP inputs
    build_cin_kernel<<<(KVH_ * NC_ * CDIM_ + 255) / 256, 256>>>(k_pos, v_pos);

    // 3. K compress MLP: W1 (512 x 2048 x 2048), W2 split-K (512 x 128 x 2048)
    gemm_v3<1, false><<<dim3(4, CDIM_ / 128, 1), 512, V3_SMEM_BYTES>>>(
        ckin, k_w1, k_b1, h1, 512, CDIM_, CDIM_, CDIM_);
    gemm_v3<0, false><<<dim3(4, 1, 8), 512, V3_SMEM_BYTES>>>(
        h1, k_w2, nullptr, ckb, 512, DH_, CDIM_, CDIM_ / 8);
    reduce_splitk<0><<<(512 * DH_ + 255) / 256, 256>>>(k_b2, ckb, 512 * DH_, DH_, 8);

    // 4. V compress MLP
    gemm_v3<1, false><<<dim3(4, CDIM_ / 128, 1), 512, V3_SMEM_BYTES>>>(
        cvin, v_w1, v_b1, h1, 512, CDIM_, CDIM_, CDIM_);
    gemm_v3<0, false><<<dim3(4, 1, 8), 512, V3_SMEM_BYTES>>>(
        h1, v_w2, nullptr, cvb, 512, DH_, CDIM_, CDIM_ / 8);
    reduce_splitk<0><<<(512 * DH_ + 255) / 256, 256>>>(v_b2, cvb, 512 * DH_, DH_, 8);

    // 5. prepend mem token
    scatter_c_kernel<<<(KVH_ * (NC_ + 1) * DH_ + 255) / 256, 256>>>(mem_kv);
    // 6. RoPE
    rope_kernel<<<dim3(S_, H_ + KVH_), 64>>>();
    // 7. compressed attention + selection
    comp_attn_kernel<<<dim3(S_, KVH_), 128>>>();
    // 8. fine attention
    fine_attn_kernel<<<dim3(S_, H_), 128>>>();
    // 9. sliding window attention
    slide_attn_kernel<<<dim3(S_, H_), 128>>>();

    // 10. gates (1024 x 96 x 4096) split-K=16 + sigmoid in reduce
    gemm_v3<0, true><<<dim3(S_ / 128, 1, 16), 512, V3_SMEM_BYTES>>>(
        hidden, w_gate, nullptr, gates, S_, 96, D_, D_ / 16);
    reduce_splitk<2><<<(S_ * 96 + 255) / 256, 256>>>(b_gate, gates, S_ * 96, 96, 16);

    // 11. combine
    combine_kernel<<<(S_ * D_ + 255) / 256, 256>>>();

    // 12. output projection (1024 x 4096 x 4096)
    gemm_v3<0, false><<<dim3(S_ / 128, D_ / 128, 1), 512, V3_SMEM_BYTES>>>(
        mid, w_o, nullptr, out, S_, D_, D_, D_);
}

// round 11
// speedup vs baseline: 1.2038x; 1.0593x over previous
#include <cuda_runtime.h>
#include <cuda_bf16.h>
#include <math.h>

// ---------------- problem constants ----------------
#define S_   1024
#define H_   32
#define KVH_ 8
#define DH_  128
#define D_   4096
#define CB_  16
#define NC_  64        // S/CB
#define SB_  16
#define NSEL_ 4
#define WIN_ 64
#define NQKV_ 6144     // H*DH + 2*KVH*DH
#define CDIM_ 2048     // CB*DH
#define NEGF (-3.402823466e38f)
#define SCALE_ 0.08838834764831844056f  // 128^-0.5

// ---------------- scratch (no allocs allowed) ----------------
__device__ float g_qkv [S_ * NQKV_];
__device__ float g_rq  [S_ * H_ * DH_];
__device__ float g_rk  [S_ * KVH_ * DH_];
__device__ float g_ckin[KVH_ * NC_ * CDIM_];
__device__ float g_cvin[KVH_ * NC_ * CDIM_];
__device__ float g_h1  [KVH_ * NC_ * CDIM_];
__device__ float g_ckb [KVH_ * NC_ * DH_];
__device__ float g_cvb [KVH_ * NC_ * DH_];
__device__ float g_ck  [KVH_ * (NC_ + 1) * DH_];
__device__ float g_cv  [KVH_ * (NC_ + 1) * DH_];
__device__ float g_cout[S_ * H_ * DH_];
__device__ float g_fout[S_ * H_ * DH_];
__device__ float g_sout[S_ * H_ * DH_];
__device__ int   g_sel [KVH_ * S_ * 5];
__device__ int   g_selok[KVH_ * S_ * 4];
__device__ float g_gates[S_ * 96];
__device__ float g_mid [S_ * D_];
__device__ float g_part[16 * 1024 * 96];   // split-K partials (max: gates)
__device__ float g_invf[64];               // rope inverse frequencies

// ---------------- helpers ----------------
__device__ __forceinline__ unsigned f2tf(float x) {
    unsigned r;
    asm("cvt.rna.tf32.f32 %0, %1;" : "=r"(r) : "f"(x));
    return r;
}

__device__ __forceinline__ void mma_tf32(float c[4], unsigned a0, unsigned a1,
                                         unsigned a2, unsigned a3,
                                         unsigned b0, unsigned b1) {
    asm volatile(
        "mma.sync.aligned.m16n8k8.row.col.f32.tf32.tf32.f32 "
        "{%0,%1,%2,%3}, {%4,%5,%6,%7}, {%8,%9}, {%0,%1,%2,%3};\n"
        : "+f"(c[0]), "+f"(c[1]), "+f"(c[2]), "+f"(c[3])
        : "r"(a0), "r"(a1), "r"(a2), "r"(a3), "r"(b0), "r"(b1));
}

// ============ TF32 GEMM v4: convert-at-STS hi/lo, 2 CTA/SM ==============
// C[M,N] = A[M,K] @ B[N,K]^T (3xTF32, fp32-accurate).
// Global traffic stays fp32; loaders LDG.128 -> cvt hi/lo once -> STS.128.
// Inner loop: pure LDS.64 -> 3x mma (R8-verified fragment indexing).
// Tile 128x64x16, 256 thr, warp tile 32x32, stride-20 uint2 smem
// (40 words = 8 mod 32 -> conflict-free LDS.64 per half-warp phase).
#define V4_BM 128
#define V4_BN 64
#define V4_BK 16
#define V4_AST 20
#define V4_ASTAGE (128 * V4_AST)     // uint2 per A stage
#define V4_BSTAGE (64 * V4_AST)
#define V4_SMEM_BYTES ((2 * (V4_ASTAGE + V4_BSTAGE)) * 8)   // 61440

#define CVT2(x, h, l) { h = f2tf(x); l = f2tf((x) - __uint_as_float(h)); }

template <int ACT, bool NGUARD>
__global__ void __launch_bounds__(256, 2)
gemm_v4(const float* __restrict__ A, const float* __restrict__ B,
        const float* __restrict__ bias, float* __restrict__ C,
        int M, int N, int K, int klen) {
    extern __shared__ uint2 sm[];
    uint2* As = sm;
    uint2* Bs = sm + 2 * V4_ASTAGE;

    const int tid = threadIdx.x;
    const int wid = tid >> 5, lane = tid & 31;
    const int warp_m = wid & 3;          // 4 slabs x 32 rows
    const int warp_n = wid >> 2;         // 2 slabs x 32 cols
    const int g = lane >> 2, tg = lane & 3;
    const int bm = blockIdx.x * V4_BM, bn = blockIdx.y * V4_BN;
    const int kglob = blockIdx.z * klen;

    // A: 2 thr/row x 8 floats; B: 4 thr/row x 4 floats
    const int arow = tid >> 1, acol = (tid & 1) * 8;
    const int brow = tid >> 2, bcol = (tid & 3) * 4;
    int brglob = bn + brow;
    int brc = NGUARD ? (brglob < N ? brglob : N - 1) : brglob;
    const bool bval = (!NGUARD) || (brglob < N);

    const float* Ap = A + (size_t)(bm + arow) * K + kglob + acol;
    const float* Bp = B + (size_t)brc * K + kglob + bcol;

    float acc[2][4][4];
#pragma unroll
    for (int i = 0; i < 2; i++)
#pragma unroll
        for (int j = 0; j < 4; j++)
#pragma unroll
            for (int e = 0; e < 4; e++) acc[i][j][e] = 0.f;

    float ar[8], br[4];
    // prefetch tile 0
    {
        float4 t0 = *(const float4*)(Ap);
        float4 t1 = *(const float4*)(Ap + 4);
        ar[0]=t0.x; ar[1]=t0.y; ar[2]=t0.z; ar[3]=t0.w;
        ar[4]=t1.x; ar[5]=t1.y; ar[6]=t1.z; ar[7]=t1.w;
        float4 t2 = *(const float4*)(Bp);
        br[0] = bval ? t2.x : 0.f; br[1] = bval ? t2.y : 0.f;
        br[2] = bval ? t2.z : 0.f; br[3] = bval ? t2.w : 0.f;
    }

    const int ntiles = klen / V4_BK;

    for (int t = 0; t < ntiles; t++) {
        const int stg = t & 1;
        __syncthreads();   // prior readers of this stage are done
        // store tile t (regs -> smem, converting to hi/lo)
        {
            uint4* da = (uint4*)&As[stg * V4_ASTAGE + arow * V4_AST + acol];
#pragma unroll
            for (int u = 0; u < 4; u++) {
                unsigned h0, l0, h1, l1;
                CVT2(ar[2 * u], h0, l0);
                CVT2(ar[2 * u + 1], h1, l1);
                da[u] = make_uint4(h0, l0, h1, l1);
            }
            uint4* db = (uint4*)&Bs[stg * V4_BSTAGE + brow * V4_AST + bcol];
#pragma unroll
            for (int u = 0; u < 2; u++) {
                unsigned h0, l0, h1, l1;
                CVT2(br[2 * u], h0, l0);
                CVT2(br[2 * u + 1], h1, l1);
                db[u] = make_uint4(h0, l0, h1, l1);
            }
        }
        __syncthreads();
        // prefetch tile t+1 (overlaps compute below)
        if (t + 1 < ntiles) {
            const float* ap = Ap + (t + 1) * V4_BK;
            const float* bp = Bp + (t + 1) * V4_BK;
            float4 t0 = *(const float4*)(ap);
            float4 t1 = *(const float4*)(ap + 4);
            ar[0]=t0.x; ar[1]=t0.y; ar[2]=t0.z; ar[3]=t0.w;
            ar[4]=t1.x; ar[5]=t1.y; ar[6]=t1.z; ar[7]=t1.w;
            float4 t2 = *(const float4*)(bp);
            br[0] = bval ? t2.x : 0.f; br[1] = bval ? t2.y : 0.f;
            br[2] = bval ? t2.z : 0.f; br[3] = bval ? t2.w : 0.f;
        }
        // compute on stage stg: pure LDS.64 + mma
        const uint2* as = As + stg * V4_ASTAGE;
        const uint2* bs = Bs + stg * V4_BSTAGE;
#pragma unroll
        for (int ks = 0; ks < 2; ks++) {
            const int cb = ks * 8;
            uint2 a[2][4];
#pragma unroll
            for (int mt = 0; mt < 2; mt++) {
                const int r0 = (warp_m * 32 + mt * 16 + g) * V4_AST;
                const int r1 = r0 + 8 * V4_AST;
                a[mt][0] = as[r0 + cb + tg];
                a[mt][1] = as[r1 + cb + tg];
                a[mt][2] = as[r0 + cb + tg + 4];
                a[mt][3] = as[r1 + cb + tg + 4];
            }
            uint2 b[4][2];
#pragma unroll
            for (int nt = 0; nt < 4; nt++) {
                const int rn = (warp_n * 32 + nt * 8 + g) * V4_AST;
                b[nt][0] = bs[rn + cb + tg];
                b[nt][1] = bs[rn + cb + tg + 4];
            }
#pragma unroll
            for (int mt = 0; mt < 2; mt++)
#pragma unroll
                for (int nt = 0; nt < 4; nt++) {
                    mma_tf32(acc[mt][nt], a[mt][0].y, a[mt][1].y, a[mt][2].y,
                             a[mt][3].y, b[nt][0].x, b[nt][1].x);
                    mma_tf32(acc[mt][nt], a[mt][0].x, a[mt][1].x, a[mt][2].x,
                             a[mt][3].x, b[nt][0].y, b[nt][1].y);
                    mma_tf32(acc[mt][nt], a[mt][0].x, a[mt][1].x, a[mt][2].x,
                             a[mt][3].x, b[nt][0].x, b[nt][1].x);
                }
        }
    }

    const bool split = (gridDim.z > 1);
#pragma unroll
    for (int mt = 0; mt < 2; mt++) {
#pragma unroll
        for (int nt = 0; nt < 4; nt++) {
#pragma unroll
            for (int e = 0; e < 4; e++) {
                int row = bm + warp_m * 32 + mt * 16 + g + ((e >= 2) ? 8 : 0);
                int col = bn + warp_n * 32 + nt * 8 + 2 * tg + (e & 1);
                if (NGUARD && col >= N) continue;
                float v = acc[mt][nt][e];
                if (split) {
                    g_part[(size_t)blockIdx.z * M * N + (size_t)row * N + col] = v;
                } else {
                    if (bias) v += bias[col];
                    if (ACT == 1) v = fmaxf(v, 0.f);
                    C[(size_t)row * N + col] = v;
                }
            }
        }
    }
}

// split-K reduce: C = act(sum_z part + bias). ACT: 0 none, 2 sigmoid
template <int ACT>
__global__ void reduce_splitk(const float* __restrict__ bias,
                              float* __restrict__ C, int MN, int N, int splits) {
    int idx = blockIdx.x * blockDim.x + threadIdx.x;
    if (idx >= MN) return;
    float s = 0.f;
    for (int z = 0; z < splits; z++) s += g_part[(size_t)z * MN + idx];
    if (bias) s += bias[idx % N];
    if (ACT == 2) s = 1.f / (1.f + expf(-s));
    C[idx] = s;
}

// ---------------- build compressed MLP inputs --------------------------------
__global__ void build_cin_kernel(const float* __restrict__ k_pos,
                                 const float* __restrict__ v_pos) {
    int idx = blockIdx.x * blockDim.x + threadIdx.x;
    if (idx >= KVH_ * NC_ * CDIM_) return;
    int r = idx >> 11, col = idx & 2047;
    int h = r >> 6, c = r & 63;
    int t = col >> 7, d = col & 127;
    int s = c * CB_ + t;
    size_t base = (size_t)s * NQKV_ + h * DH_ + d;
    int pidx = (h * CB_ + t) * DH_ + d;
    g_ckin[idx] = g_qkv[base + 4096] + k_pos[pidx];
    g_cvin[idx] = g_qkv[base + 5120] + v_pos[pidx];
}

// ---------------- scatter compressed K/V (prepend mem token) -----------------
__global__ void scatter_c_kernel(const float* __restrict__ mem_kv) {
    int idx = blockIdx.x * blockDim.x + threadIdx.x;
    if (idx >= KVH_ * (NC_ + 1) * DH_) return;
    int d = idx & 127, jh = idx >> 7;
    int h = jh / (NC_ + 1), j = jh % (NC_ + 1);
    float kv, vv;
    if (j == 0) {
        kv = mem_kv[h * DH_ + d];
        vv = mem_kv[KVH_ * DH_ + h * DH_ + d];
    } else {
        int r = (h * NC_ + (j - 1)) * DH_ + d;
        kv = g_ckb[r];
        vv = g_cvb[r];
    }
    g_ck[idx] = kv;
    g_cv[idx] = vv;
}

// ---------------- RoPE (interleaved, theta=10000) ----------------------------
__global__ void invf_kernel() {
    int p = threadIdx.x;
    g_invf[p] = (float)pow(10000.0, -(double)(2 * p) / 128.0);
}

__global__ void rope_kernel() {     // grid: S_, block: 256
    __shared__ float cs_[64], sn_[64];
    int i = blockIdx.x, tid = threadIdx.x;
    if (tid < 64) {
        float ang = (float)i * g_invf[tid];
        sincosf(ang, &sn_[tid], &cs_[tid]);
    }
    __syncthreads();
    for (int u = tid; u < (H_ + KVH_) * 64; u += 256) {
        int y = u >> 6, p = u & 63;
        const float* src;
        float* dst;
        if (y < H_) {
            src = g_qkv + (size_t)i * NQKV_ + y * DH_;
            dst = g_rq + ((size_t)i * H_ + y) * DH_;
        } else {
            src = g_qkv + (size_t)i * NQKV_ + 4096 + (y - H_) * DH_;
            dst = g_rk + ((size_t)i * KVH_ + (y - H_)) * DH_;
        }
        float x0 = src[2 * p], x1 = src[2 * p + 1];
        dst[2 * p]     = x0 * cs_[p] - x1 * sn_[p];
        dst[2 * p + 1] = x1 * cs_[p] + x0 * sn_[p];
    }
}

// ---------------- compressed attention + importance top-k --------------------
__global__ void comp_attn_kernel() {
    int i = blockIdx.x;
    int h = blockIdx.y;
    int tid = threadIdx.x;
    int g = tid >> 5, lane = tid & 31;
    __shared__ float sim[4][65];
    __shared__ float imp[64];
    __shared__ float prob[64];
    __shared__ float red[2];

    const float* qp = g_qkv + (size_t)i * NQKV_ + (h * 4 + g) * DH_;
    float q0 = qp[lane], q1 = qp[lane + 32], q2 = qp[lane + 64], q3 = qp[lane + 96];

    for (int j = 0; j < 65; j++) {
        const float* kp = g_ck + (h * 65 + j) * DH_;
        float d = q0 * kp[lane] + q1 * kp[lane + 32] + q2 * kp[lane + 64] + q3 * kp[lane + 96];
#pragma unroll
        for (int o = 16; o > 0; o >>= 1) d += __shfl_down_sync(0xffffffffu, d, o);
        if (lane == 0) {
            bool vis = (j == 0) || (i >= j * CB_);
            sim[g][j] = vis ? d * SCALE_ : NEGF;
        }
    }
    __syncwarp();

    float m = NEGF;
    for (int j = lane; j < 65; j += 32) m = fmaxf(m, sim[g][j]);
#pragma unroll
    for (int o = 16; o > 0; o >>= 1) m = fmaxf(m, __shfl_xor_sync(0xffffffffu, m, o));
    float den = 0.f;
    for (int j = lane; j < 65; j += 32) den += expf(sim[g][j] - m);
#pragma unroll
    for (int o = 16; o > 0; o >>= 1) den += __shfl_xor_sync(0xffffffffu, den, o);
    float invden = 1.f / den;

    float o0 = 0, o1 = 0, o2 = 0, o3 = 0;
    for (int j = 0; j < 65; j++) {
        float p = expf(sim[g][j] - m) * invden;
        const float* vp = g_cv + (h * 65 + j) * DH_;
        o0 += p * vp[lane];
        o1 += p * vp[lane + 32];
        o2 += p * vp[lane + 64];
        o3 += p * vp[lane + 96];
    }
    float* op = g_cout + ((size_t)i * H_ + h * 4 + g) * DH_;
    op[lane] = o0; op[lane + 32] = o1; op[lane + 64] = o2; op[lane + 96] = o3;

    __syncthreads();

    if (tid < 64) {
        float s = sim[0][tid + 1] + sim[1][tid + 1] + sim[2][tid + 1] + sim[3][tid + 1];
        imp[tid] = 0.25f * s;
    }
    __syncthreads();

    if (tid == 0) {
        float mm = -1000.f;
        for (int j = 0; j < 64; j++) mm = fmaxf(mm, imp[j]);
        float dd = expf(-1000.f - mm);
        for (int j = 0; j < 64; j++) dd += expf(imp[j] - mm);
        red[0] = mm;
        red[1] = 1.f / dd;
    }
    __syncthreads();
    if (tid < 64) prob[tid] = expf(imp[tid] - red[0]) * red[1];
    __syncthreads();

    if (tid == 0) {
        unsigned long long used = 0ull;
        int* sp = g_sel + (h * S_ + i) * 5;
        int* okp = g_selok + (h * S_ + i) * 4;
        for (int r = 0; r < NSEL_; r++) {
            float bp = -1.f;
            int bj = 0;
            for (int j = 0; j < 64; j++) {
                if ((used >> j) & 1ull) continue;
                float p = prob[j];
                if (p > bp) { bp = p; bj = j; }   // strict > : lowest-index tiebreak
            }
            used |= 1ull << bj;
            sp[r] = bj;
            okp[r] = (bp > 1e-10f) ? 1 : 0;
        }
        sp[4] = i >> 4;
    }
}

// ---------------- fine (selected-block) attention ----------------------------
__global__ void fine_attn_kernel() {
    int i = blockIdx.x, qh = blockIdx.y;
    int h = qh >> 2;
    int tid = threadIdx.x;
    int w = tid >> 5, lane = tid & 31;
    __shared__ float sim[80];
    __shared__ int sblk[5];
    __shared__ int sok[4];
    __shared__ float ssoft[2];

    if (tid < 5) sblk[tid] = g_sel[(h * S_ + i) * 5 + tid];
    if (tid < 4) sok[tid] = g_selok[(h * S_ + i) * 4 + tid];
    __syncthreads();

    const float* qp = g_rq + ((size_t)i * H_ + qh) * DH_;
    float q0 = qp[lane], q1 = qp[lane + 32], q2 = qp[lane + 64], q3 = qp[lane + 96];

    for (int j = w * 20; j < w * 20 + 20; j++) {
        int r = j >> 4, t = j & 15;
        int skey = sblk[r] * SB_ + t;
        const float* kp = g_rk + ((size_t)skey * KVH_ + h) * DH_;
        float d = q0 * kp[lane] + q1 * kp[lane + 32] + q2 * kp[lane + 64] + q3 * kp[lane + 96];
#pragma unroll
        for (int o = 16; o > 0; o >>= 1) d += __shfl_down_sync(0xffffffffu, d, o);
        if (lane == 0) {
            bool vis = (r < 4) ? (sok[r] != 0) : (t <= (i & 15));
            sim[j] = vis ? d * SCALE_ : NEGF;
        }
    }
    __syncthreads();

    if (w == 0) {
        float m = NEGF;
        for (int j = lane; j < 80; j += 32) m = fmaxf(m, sim[j]);
#pragma unroll
        for (int o = 16; o > 0; o >>= 1) m = fmaxf(m, __shfl_xor_sync(0xffffffffu, m, o));
        float dd = 0.f;
        for (int j = lane; j < 80; j += 32) dd += expf(sim[j] - m);
#pragma unroll
        for (int o = 16; o > 0; o >>= 1) dd += __shfl_xor_sync(0xffffffffu, dd, o);
        if (lane == 0) { ssoft[0] = m; ssoft[1] = 1.f / dd; }
    }
    __syncthreads();
    if (tid < 80) sim[tid] = expf(sim[tid] - ssoft[0]) * ssoft[1];
    __syncthreads();

    float acc = 0.f;
    int d = tid;
    for (int j = 0; j < 80; j++) {
        int r = j >> 4, t = j & 15;
        int skey = sblk[r] * SB_ + t;
        acc += sim[j] * g_qkv[(size_t)skey * NQKV_ + 5120 + h * DH_ + d];
    }
    g_fout[((size_t)i * H_ + qh) * DH_ + d] = acc;
}

// ---------------- sliding-window attention (65 keys, clipped) ----------------
__global__ void slide_attn_kernel() {
    int i = blockIdx.x, qh = blockIdx.y;
    int h = qh >> 2;
    int tid = threadIdx.x;
    int w = tid >> 5, lane = tid & 31;
    __shared__ float sim[65];
    __shared__ float ssoft[2];

    int j0 = i - WIN_;
    if (j0 < 0) j0 = 0;
    int nj = i - j0 + 1;

    const float* qp = g_rq + ((size_t)i * H_ + qh) * DH_;
    float q0 = qp[lane], q1 = qp[lane + 32], q2 = qp[lane + 64], q3 = qp[lane + 96];

    for (int j = w; j < nj; j += 4) {
        int s = j0 + j;
        const float* kp = g_rk + ((size_t)s * KVH_ + h) * DH_;
        float d = q0 * kp[lane] + q1 * kp[lane + 32] + q2 * kp[lane + 64] + q3 * kp[lane + 96];
#pragma unroll
        for (int o = 16; o > 0; o >>= 1) d += __shfl_down_sync(0xffffffffu, d, o);
        if (lane == 0) sim[j] = d * SCALE_;
    }
    __syncthreads();

    if (w == 0) {
        float m = NEGF;
        for (int j = lane; j < nj; j += 32) m = fmaxf(m, sim[j]);
#pragma unroll
        for (int o = 16; o > 0; o >>= 1) m = fmaxf(m, __shfl_xor_sync(0xffffffffu, m, o));
        float dd = 0.f;
        for (int j = lane; j < nj; j += 32) dd += expf(sim[j] - m);
#pragma unroll
        for (int o = 16; o > 0; o >>= 1) dd += __shfl_xor_sync(0xffffffffu, dd, o);
        if (lane == 0) { ssoft[0] = m; ssoft[1] = 1.f / dd; }
    }
    __syncthreads();
    if (tid < nj) sim[tid] = expf(sim[tid] - ssoft[0]) * ssoft[1];
    __syncthreads();

    float acc = 0.f;
    int d = tid;
    for (int j = 0; j < nj; j++)
        acc += sim[j] * g_qkv[(size_t)(j0 + j) * NQKV_ + 5120 + h * DH_ + d];
    g_sout[((size_t)i * H_ + qh) * DH_ + d] = acc;
}

// ---------------- gate-combine ------------------------------------------------
__global__ void combine_kernel() {
    int idx = blockIdx.x * blockDim.x + threadIdx.x;
    if (idx >= S_ * D_) return;
    int i = idx >> 12, hd = idx & 4095, hh = hd >> 7;
    const float* gp = g_gates + i * 96 + hh * 3;
    g_mid[idx] = gp[0] * g_cout[idx] + gp[1] * g_fout[idx] + gp[2] * g_sout[idx];
}

// ---------------- launch ------------------------------------------------------
extern "C" void kernel_launch(void* const* d_in, const int* in_sizes, int n_in,
                              void* d_out, int out_size) {
    const float* hidden = (const float*)d_in[0];
    const float* w_qkv  = (const float*)d_in[1];
    const float* w_o    = (const float*)d_in[2];
    const float* k_pos  = (const float*)d_in[3];
    const float* v_pos  = (const float*)d_in[4];
    const float* k_w1   = (const float*)d_in[5];
    const float* k_b1   = (const float*)d_in[6];
    const float* k_w2   = (const float*)d_in[7];
    const float* k_b2   = (const float*)d_in[8];
    const float* v_w1   = (const float*)d_in[9];
    const float* v_b1   = (const float*)d_in[10];
    const float* v_w2   = (const float*)d_in[11];
    const float* v_b2   = (const float*)d_in[12];
    const float* mem_kv = (const float*)d_in[13];
    const float* w_gate = (const float*)d_in[14];
    const float* b_gate = (const float*)d_in[15];
    float* out = (float*)d_out;

    float *qkv, *ckin, *cvin, *h1, *ckb, *cvb, *gates, *mid;
    cudaGetSymbolAddress((void**)&qkv,   g_qkv);
    cudaGetSymbolAddress((void**)&ckin,  g_ckin);
    cudaGetSymbolAddress((void**)&cvin,  g_cvin);
    cudaGetSymbolAddress((void**)&h1,    g_h1);
    cudaGetSymbolAddress((void**)&ckb,   g_ckb);
    cudaGetSymbolAddress((void**)&cvb,   g_cvb);
    cudaGetSymbolAddress((void**)&gates, g_gates);
    cudaGetSymbolAddress((void**)&mid,   g_mid);

    cudaFuncSetAttribute(gemm_v4<0, false>,
                         cudaFuncAttributeMaxDynamicSharedMemorySize, V4_SMEM_BYTES);
    cudaFuncSetAttribute(gemm_v4<1, false>,
                         cudaFuncAttributeMaxDynamicSharedMemorySize, V4_SMEM_BYTES);
    cudaFuncSetAttribute(gemm_v4<0, true>,
                         cudaFuncAttributeMaxDynamicSharedMemorySize, V4_SMEM_BYTES);

    // 0. rope inverse-frequency table
    invf_kernel<<<1, 64>>>();

    // 1. QKV projection (1024 x 6144 x 4096)
    gemm_v4<0, false><<<dim3(S_ / V4_BM, NQKV_ / V4_BN, 1), 256, V4_SMEM_BYTES>>>(
        hidden, w_qkv, nullptr, qkv, S_, NQKV_, D_, D_);

    // 2. compressed MLP inputs
    build_cin_kernel<<<(KVH_ * NC_ * CDIM_ + 255) / 256, 256>>>(k_pos, v_pos);

    // 3. K compress MLP: W1 (512 x 2048 x 2048), W2 split-K (512 x 128 x 2048)
    gemm_v4<1, false><<<dim3(4, CDIM_ / V4_BN, 1), 256, V4_SMEM_BYTES>>>(
        ckin, k_w1, k_b1, h1, 512, CDIM_, CDIM_, CDIM_);
    gemm_v4<0, false><<<dim3(4, 2, 8), 256, V4_SMEM_BYTES>>>(
        h1, k_w2, nullptr, ckb, 512, DH_, CDIM_, CDIM_ / 8);
    reduce_splitk<0><<<(512 * DH_ + 255) / 256, 256>>>(k_b2, ckb, 512 * DH_, DH_, 8);

    // 4. V compress MLP
    gemm_v4<1, false><<<dim3(4, CDIM_ / V4_BN, 1), 256, V4_SMEM_BYTES>>>(
        cvin, v_w1, v_b1, h1, 512, CDIM_, CDIM_, CDIM_);
    gemm_v4<0, false><<<dim3(4, 2, 8), 256, V4_SMEM_BYTES>>>(
        h1, v_w2, nullptr, cvb, 512, DH_, CDIM_, CDIM_ / 8);
    reduce_splitk<0><<<(512 * DH_ + 255) / 256, 256>>>(v_b2, cvb, 512 * DH_, DH_, 8);

    // 5. prepend mem token
    scatter_c_kernel<<<(KVH_ * (NC_ + 1) * DH_ + 255) / 256, 256>>>(mem_kv);
    // 6. RoPE
    rope_kernel<<<S_, 256>>>();
    // 7. compressed attention + selection
    comp_attn_kernel<<<dim3(S_, KVH_), 128>>>();
    // 8. fine attention
    fine_attn_kernel<<<dim3(S_, H_), 128>>>();
    // 9. sliding window attention
    slide_attn_kernel<<<dim3(S_, H_), 128>>>();

    // 10. gates (1024 x 96 x 4096) split-K=16 + sigmoid in reduce
    gemm_v4<0, true><<<dim3(S_ / V4_BM, 2, 16), 256, V4_SMEM_BYTES>>>(
        hidden, w_gate, nullptr, gates, S_, 96, D_, D_ / 16);
    reduce_splitk<2><<<(S_ * 96 + 255) / 256, 256>>>(b_gate, gates, S_ * 96, 96, 16);

    // 11. combine
    combine_kernel<<<(S_ * D_ + 255) / 256, 256>>>();

    // 12. output projection (1024 x 4096 x 4096)
    gemm_v4<0, false><<<dim3(S_ / V4_BM, D_ / V4_BN, 1), 256, V4_SMEM_BYTES>>>(
        mid, w_o, nullptr, out, S_, D_, D_, D_);
}

// round 12
// speedup vs baseline: 1.8685x; 1.5522x over previous
#include <cuda_runtime.h>
#include <cuda_bf16.h>
#include <math.h>

// ---------------- problem constants ----------------
#define S_   1024
#define H_   32
#define KVH_ 8
#define DH_  128
#define D_   4096
#define CB_  16
#define NC_  64        // S/CB
#define SB_  16
#define NSEL_ 4
#define WIN_ 64
#define NQKV_ 6144     // H*DH + 2*KVH*DH
#define CDIM_ 2048     // CB*DH
#define NEGF (-3.402823466e38f)
#define SCALE_ 0.08838834764831844056f  // 128^-0.5

// ---------------- scratch (no allocs allowed) ----------------
__device__ float g_qkv [S_ * NQKV_];
__device__ float g_rq  [S_ * H_ * DH_];
__device__ float g_rk  [S_ * KVH_ * DH_];
__device__ float g_ckin[KVH_ * NC_ * CDIM_];
__device__ float g_cvin[KVH_ * NC_ * CDIM_];
__device__ float g_h1  [KVH_ * NC_ * CDIM_];
__device__ float g_ckb [KVH_ * NC_ * DH_];
__device__ float g_cvb [KVH_ * NC_ * DH_];
__device__ float g_ck  [KVH_ * (NC_ + 1) * DH_];
__device__ float g_cv  [KVH_ * (NC_ + 1) * DH_];
__device__ float g_cout[S_ * H_ * DH_];
__device__ float g_fout[S_ * H_ * DH_];
__device__ float g_sout[S_ * H_ * DH_];
__device__ int   g_sel [KVH_ * S_ * 5];
__device__ int   g_selok[KVH_ * S_ * 4];
__device__ float g_gates[S_ * 96];
__device__ float g_mid [S_ * D_];
__device__ float g_part[16 * 1024 * 96];   // split-K partials (max: gates)
__device__ float g_invf[64];               // rope inverse frequencies

// bf16 hi/lo planes (pre-split; 4B/elem total — same global bytes as fp32)
__device__ __nv_bfloat16 g_Bh [NQKV_ * D_];   // weights (reused serially)
__device__ __nv_bfloat16 g_Bl [NQKV_ * D_];
__device__ __nv_bfloat16 g_AXh[S_ * D_];      // hidden, later mid
__device__ __nv_bfloat16 g_AXl[S_ * D_];
__device__ __nv_bfloat16 g_ACh[KVH_ * NC_ * CDIM_];   // ckin / cvin
__device__ __nv_bfloat16 g_ACl[KVH_ * NC_ * CDIM_];
__device__ __nv_bfloat16 g_AHh[KVH_ * NC_ * CDIM_];   // h1
__device__ __nv_bfloat16 g_AHl[KVH_ * NC_ * CDIM_];

// ---------------- helpers ----------------
__device__ __forceinline__ void mma_bf16(float c[4], const unsigned a[4],
                                         const unsigned b[2]) {
    asm volatile(
        "mma.sync.aligned.m16n8k16.row.col.f32.bf16.bf16.f32 "
        "{%0,%1,%2,%3}, {%4,%5,%6,%7}, {%8,%9}, {%0,%1,%2,%3};\n"
        : "+f"(c[0]), "+f"(c[1]), "+f"(c[2]), "+f"(c[3])
        : "r"(a[0]), "r"(a[1]), "r"(a[2]), "r"(a[3]), "r"(b[0]), "r"(b[1]));
}

__device__ __forceinline__ void cp16(unsigned dst, const void* src, int zfill) {
    asm volatile("cp.async.ca.shared.global [%0], [%1], 16, %2;\n"
                 :: "r"(dst), "l"(src), "r"(zfill));
}

// ---------------- hi/lo bf16 split pre-pass (4 floats/thread) ----------------
__global__ void split_bf16_kernel(const float* __restrict__ src,
                                  __nv_bfloat16* __restrict__ dh,
                                  __nv_bfloat16* __restrict__ dl, int n4) {
    int i = blockIdx.x * blockDim.x + threadIdx.x;
    if (i >= n4) return;
    float4 v = ((const float4*)src)[i];
    float x[4] = {v.x, v.y, v.z, v.w};
    unsigned hb[4], lb[4];
#pragma unroll
    for (int j = 0; j < 4; j++) {
        __nv_bfloat16 h = __float2bfloat16(x[j]);
        __nv_bfloat16 l = __float2bfloat16(x[j] - __bfloat162float(h));
        hb[j] = __bfloat16_as_ushort(h);
        lb[j] = __bfloat16_as_ushort(l);
    }
    ((uint2*)dh)[i] = make_uint2((hb[1] << 16) | hb[0], (hb[3] << 16) | hb[2]);
    ((uint2*)dl)[i] = make_uint2((lb[1] << 16) | lb[0], (lb[3] << 16) | lb[2]);
}

// ============ bf16x3 GEMM v5: pre-split planes + m16n8k16 ===================
// C[M,N] = A[M,K] @ B[N,K]^T, 3 products (lo*hi + hi*lo + hi*hi) ~ fp32.
// Tile 128x64x32, 256 thr, warp tile 32x32 (warp_m=wid&3, warp_n=wid>>2).
// smem rows: 32 bf16 + 8 pad = 80B (20 words): frag banks 20g+t distinct.
// Double-buffered cp.async; 2 CTA/SM.
// smem layout (bytes): A planes [2 stg][hi,lo][128*80]=40960; B base 40960,
// [2 stg][hi,lo][64*80]=20480. total 61440.
#define V5_SMEM_BYTES 61440

template <int ACT, bool NGUARD>
__global__ void __launch_bounds__(256, 2)
gemm_v5(const __nv_bfloat16* __restrict__ Ah, const __nv_bfloat16* __restrict__ Al,
        const __nv_bfloat16* __restrict__ Bh, const __nv_bfloat16* __restrict__ Bl,
        const float* __restrict__ bias, float* __restrict__ C,
        int M, int N, int K, int klen) {
    extern __shared__ __nv_bfloat16 smb[];

    const int tid = threadIdx.x;
    const int wid = tid >> 5, lane = tid & 31;
    const int warp_m = wid & 3;          // 4 slabs x 32 rows
    const int warp_n = wid >> 2;         // 2 slabs x 32 cols
    const int g = lane >> 2, tg = lane & 3;
    const int bm = blockIdx.x * 128, bn = blockIdx.y * 64;
    const int kglob = blockIdx.z * klen;

    // loaders: A 2 thr/row x 16 bf16 (2x16B per plane); B 4 thr/row x 8 (1x16B)
    const int arow = tid >> 1, acol = (tid & 1) * 16;
    const int brow = tid >> 2, bcol = (tid & 3) * 8;
    int brglob = bn + brow;
    int brc = NGUARD ? (brglob < N ? brglob : N - 1) : brglob;
    const int bzf = (!NGUARD || brglob < N) ? 16 : 0;

    const __nv_bfloat16* Aph = Ah + (size_t)(bm + arow) * K + kglob + acol;
    const __nv_bfloat16* Apl = Al + (size_t)(bm + arow) * K + kglob + acol;
    const __nv_bfloat16* Bph = Bh + (size_t)brc * K + kglob + bcol;
    const __nv_bfloat16* Bpl = Bl + (size_t)brc * K + kglob + bcol;

    const unsigned sbase = (unsigned)__cvta_generic_to_shared(smb);
    const unsigned sa = sbase + (unsigned)(arow * 80 + acol * 2);
    const unsigned sb = sbase + 40960u + (unsigned)(brow * 80 + bcol * 2);

    float acc[2][4][4];
#pragma unroll
    for (int i = 0; i < 2; i++)
#pragma unroll
        for (int j = 0; j < 4; j++)
#pragma unroll
            for (int e = 0; e < 4; e++) acc[i][j][e] = 0.f;

    const int ntiles = klen / 32;

#define V5LOAD(stg, t)                                                       \
    do {                                                                     \
        const __nv_bfloat16* aph = Aph + (t) * 32;                           \
        const __nv_bfloat16* apl = Apl + (t) * 32;                           \
        const __nv_bfloat16* bph = Bph + (t) * 32;                           \
        const __nv_bfloat16* bpl = Bpl + (t) * 32;                           \
        unsigned adh = sa + (stg) * 20480u;                                  \
        unsigned adl = adh + 10240u;                                         \
        unsigned bdh = sb + (stg) * 10240u;                                  \
        unsigned bdl = bdh + 5120u;                                          \
        cp16(adh, aph, 16);        cp16(adh + 16u, aph + 8, 16);             \
        cp16(adl, apl, 16);        cp16(adl + 16u, apl + 8, 16);             \
        cp16(bdh, bph, bzf);       cp16(bdl, bpl, bzf);                      \
        asm volatile("cp.async.commit_group;\n");                            \
    } while (0)

    V5LOAD(0, 0);

    const unsigned* W = (const unsigned*)smb;

    for (int t = 0; t < ntiles; t++) {
        const int stg = t & 1;
        if (t + 1 < ntiles) {
            V5LOAD((t + 1) & 1, t + 1);
            asm volatile("cp.async.wait_group 1;\n");
        } else {
            asm volatile("cp.async.wait_group 0;\n");
        }
        __syncthreads();

        // word-offset bases for this stage (uint32 units)
        const unsigned* wAh = W + stg * 5120;
        const unsigned* wAl = wAh + 2560;
        const unsigned* wBh = W + 10240 + stg * 2560;
        const unsigned* wBl = wBh + 1280;

#pragma unroll
        for (int ks = 0; ks < 2; ks++) {
            const int koff = ks * 8 + tg;
            unsigned ah[2][4], al[2][4];
#pragma unroll
            for (int mt = 0; mt < 2; mt++) {
                const int rw = (warp_m * 32 + mt * 16 + g) * 20 + koff;
                ah[mt][0] = wAh[rw];        ah[mt][1] = wAh[rw + 160];
                ah[mt][2] = wAh[rw + 4];    ah[mt][3] = wAh[rw + 164];
                al[mt][0] = wAl[rw];        al[mt][1] = wAl[rw + 160];
                al[mt][2] = wAl[rw + 4];    al[mt][3] = wAl[rw + 164];
            }
            unsigned bh[4][2], bl[4][2];
#pragma unroll
            for (int nt = 0; nt < 4; nt++) {
                const int rw = (warp_n * 32 + nt * 8 + g) * 20 + koff;
                bh[nt][0] = wBh[rw];        bh[nt][1] = wBh[rw + 4];
                bl[nt][0] = wBl[rw];        bl[nt][1] = wBl[rw + 4];
            }
#pragma unroll
            for (int mt = 0; mt < 2; mt++)
#pragma unroll
                for (int nt = 0; nt < 4; nt++) {
                    mma_bf16(acc[mt][nt], al[mt], bh[nt]);
                    mma_bf16(acc[mt][nt], ah[mt], bl[nt]);
                    mma_bf16(acc[mt][nt], ah[mt], bh[nt]);
                }
        }
        __syncthreads();
    }
#undef V5LOAD

    const bool split = (gridDim.z > 1);
#pragma unroll
    for (int mt = 0; mt < 2; mt++) {
#pragma unroll
        for (int nt = 0; nt < 4; nt++) {
#pragma unroll
            for (int e = 0; e < 4; e++) {
                int row = bm + warp_m * 32 + mt * 16 + g + ((e >= 2) ? 8 : 0);
                int col = bn + warp_n * 32 + nt * 8 + 2 * tg + (e & 1);
                if (NGUARD && col >= N) continue;
                float v = acc[mt][nt][e];
                if (split) {
                    g_part[(size_t)blockIdx.z * M * N + (size_t)row * N + col] = v;
                } else {
                    if (bias) v += bias[col];
                    if (ACT == 1) v = fmaxf(v, 0.f);
                    C[(size_t)row * N + col] = v;
                }
            }
        }
    }
}

// split-K reduce: C = act(sum_z part + bias). ACT: 0 none, 2 sigmoid
template <int ACT>
__global__ void reduce_splitk(const float* __restrict__ bias,
                              float* __restrict__ C, int MN, int N, int splits) {
    int idx = blockIdx.x * blockDim.x + threadIdx.x;
    if (idx >= MN) return;
    float s = 0.f;
    for (int z = 0; z < splits; z++) s += g_part[(size_t)z * MN + idx];
    if (bias) s += bias[idx % N];
    if (ACT == 2) s = 1.f / (1.f + expf(-s));
    C[idx] = s;
}

// ---------------- build compressed MLP inputs --------------------------------
__global__ void build_cin_kernel(const float* __restrict__ k_pos,
                                 const float* __restrict__ v_pos) {
    int idx = blockIdx.x * blockDim.x + threadIdx.x;
    if (idx >= KVH_ * NC_ * CDIM_) return;
    int r = idx >> 11, col = idx & 2047;
    int h = r >> 6, c = r & 63;
    int t = col >> 7, d = col & 127;
    int s = c * CB_ + t;
    size_t base = (size_t)s * NQKV_ + h * DH_ + d;
    int pidx = (h * CB_ + t) * DH_ + d;
    g_ckin[idx] = g_qkv[base + 4096] + k_pos[pidx];
    g_cvin[idx] = g_qkv[base + 5120] + v_pos[pidx];
}

// ---------------- scatter compressed K/V (prepend mem token) -----------------
__global__ void scatter_c_kernel(const float* __restrict__ mem_kv) {
    int idx = blockIdx.x * blockDim.x + threadIdx.x;
    if (idx >= KVH_ * (NC_ + 1) * DH_) return;
    int d = idx & 127, jh = idx >> 7;
    int h = jh / (NC_ + 1), j = jh % (NC_ + 1);
    float kv, vv;
    if (j == 0) {
        kv = mem_kv[h * DH_ + d];
        vv = mem_kv[KVH_ * DH_ + h * DH_ + d];
    } else {
        int r = (h * NC_ + (j - 1)) * DH_ + d;
        kv = g_ckb[r];
        vv = g_cvb[r];
    }
    g_ck[idx] = kv;
    g_cv[idx] = vv;
}

// ---------------- RoPE (interleaved, theta=10000) ----------------------------
__global__ void invf_kernel() {
    int p = threadIdx.x;
    g_invf[p] = (float)pow(10000.0, -(double)(2 * p) / 128.0);
}

__global__ void rope_kernel() {     // grid: S_, block: 256
    __shared__ float cs_[64], sn_[64];
    int i = blockIdx.x, tid = threadIdx.x;
    if (tid < 64) {
        float ang = (float)i * g_invf[tid];
        sincosf(ang, &sn_[tid], &cs_[tid]);
    }
    __syncthreads();
    for (int u = tid; u < (H_ + KVH_) * 64; u += 256) {
        int y = u >> 6, p = u & 63;
        const float* src;
        float* dst;
        if (y < H_) {
            src = g_qkv + (size_t)i * NQKV_ + y * DH_;
            dst = g_rq + ((size_t)i * H_ + y) * DH_;
        } else {
            src = g_qkv + (size_t)i * NQKV_ + 4096 + (y - H_) * DH_;
            dst = g_rk + ((size_t)i * KVH_ + (y - H_)) * DH_;
        }
        float x0 = src[2 * p], x1 = src[2 * p + 1];
        dst[2 * p]     = x0 * cs_[p] - x1 * sn_[p];
        dst[2 * p + 1] = x1 * cs_[p] + x0 * sn_[p];
    }
}

// ---------------- compressed attention + importance top-k --------------------
__global__ void comp_attn_kernel() {
    int i = blockIdx.x;
    int h = blockIdx.y;
    int tid = threadIdx.x;
    int g = tid >> 5, lane = tid & 31;
    __shared__ float sim[4][65];
    __shared__ float imp[64];
    __shared__ float prob[64];
    __shared__ float red[2];

    const float* qp = g_qkv + (size_t)i * NQKV_ + (h * 4 + g) * DH_;
    float q0 = qp[lane], q1 = qp[lane + 32], q2 = qp[lane + 64], q3 = qp[lane + 96];

    for (int j = 0; j < 65; j++) {
        const float* kp = g_ck + (h * 65 + j) * DH_;
        float d = q0 * kp[lane] + q1 * kp[lane + 32] + q2 * kp[lane + 64] + q3 * kp[lane + 96];
#pragma unroll
        for (int o = 16; o > 0; o >>= 1) d += __shfl_down_sync(0xffffffffu, d, o);
        if (lane == 0) {
            bool vis = (j == 0) || (i >= j * CB_);
            sim[g][j] = vis ? d * SCALE_ : NEGF;
        }
    }
    __syncwarp();

    float m = NEGF;
    for (int j = lane; j < 65; j += 32) m = fmaxf(m, sim[g][j]);
#pragma unroll
    for (int o = 16; o > 0; o >>= 1) m = fmaxf(m, __shfl_xor_sync(0xffffffffu, m, o));
    float den = 0.f;
    for (int j = lane; j < 65; j += 32) den += expf(sim[g][j] - m);
#pragma unroll
    for (int o = 16; o > 0; o >>= 1) den += __shfl_xor_sync(0xffffffffu, den, o);
    float invden = 1.f / den;

    float o0 = 0, o1 = 0, o2 = 0, o3 = 0;
    for (int j = 0; j < 65; j++) {
        float p = expf(sim[g][j] - m) * invden;
        const float* vp = g_cv + (h * 65 + j) * DH_;
        o0 += p * vp[lane];
        o1 += p * vp[lane + 32];
        o2 += p * vp[lane + 64];
        o3 += p * vp[lane + 96];
    }
    float* op = g_cout + ((size_t)i * H_ + h * 4 + g) * DH_;
    op[lane] = o0; op[lane + 32] = o1; op[lane + 64] = o2; op[lane + 96] = o3;

    __syncthreads();

    if (tid < 64) {
        float s = sim[0][tid + 1] + sim[1][tid + 1] + sim[2][tid + 1] + sim[3][tid + 1];
        imp[tid] = 0.25f * s;
    }
    __syncthreads();

    if (tid == 0) {
        float mm = -1000.f;
        for (int j = 0; j < 64; j++) mm = fmaxf(mm, imp[j]);
        float dd = expf(-1000.f - mm);
        for (int j = 0; j < 64; j++) dd += expf(imp[j] - mm);
        red[0] = mm;
        red[1] = 1.f / dd;
    }
    __syncthreads();
    if (tid < 64) prob[tid] = expf(imp[tid] - red[0]) * red[1];
    __syncthreads();

    if (tid == 0) {
        unsigned long long used = 0ull;
        int* sp = g_sel + (h * S_ + i) * 5;
        int* okp = g_selok + (h * S_ + i) * 4;
        for (int r = 0; r < NSEL_; r++) {
            float bp = -1.f;
            int bj = 0;
            for (int j = 0; j < 64; j++) {
                if ((used >> j) & 1ull) continue;
                float p = prob[j];
                if (p > bp) { bp = p; bj = j; }   // strict > : lowest-index tiebreak
            }
            used |= 1ull << bj;
            sp[r] = bj;
            okp[r] = (bp > 1e-10f) ? 1 : 0;
        }
        sp[4] = i >> 4;
    }
}

// ---------------- fine (selected-block) attention ----------------------------
__global__ void fine_attn_kernel() {
    int i = blockIdx.x, qh = blockIdx.y;
    int h = qh >> 2;
    int tid = threadIdx.x;
    int w = tid >> 5, lane = tid & 31;
    __shared__ float sim[80];
    __shared__ int sblk[5];
    __shared__ int sok[4];
    __shared__ float ssoft[2];

    if (tid < 5) sblk[tid] = g_sel[(h * S_ + i) * 5 + tid];
    if (tid < 4) sok[tid] = g_selok[(h * S_ + i) * 4 + tid];
    __syncthreads();

    const float* qp = g_rq + ((size_t)i * H_ + qh) * DH_;
    float q0 = qp[lane], q1 = qp[lane + 32], q2 = qp[lane + 64], q3 = qp[lane + 96];

    for (int j = w * 20; j < w * 20 + 20; j++) {
        int r = j >> 4, t = j & 15;
        int skey = sblk[r] * SB_ + t;
        const float* kp = g_rk + ((size_t)skey * KVH_ + h) * DH_;
        float d = q0 * kp[lane] + q1 * kp[lane + 32] + q2 * kp[lane + 64] + q3 * kp[lane + 96];
#pragma unroll
        for (int o = 16; o > 0; o >>= 1) d += __shfl_down_sync(0xffffffffu, d, o);
        if (lane == 0) {
            bool vis = (r < 4) ? (sok[r] != 0) : (t <= (i & 15));
            sim[j] = vis ? d * SCALE_ : NEGF;
        }
    }
    __syncthreads();

    if (w == 0) {
        float m = NEGF;
        for (int j = lane; j < 80; j += 32) m = fmaxf(m, sim[j]);
#pragma unroll
        for (int o = 16; o > 0; o >>= 1) m = fmaxf(m, __shfl_xor_sync(0xffffffffu, m, o));
        float dd = 0.f;
        for (int j = lane; j < 80; j += 32) dd += expf(sim[j] - m);
#pragma unroll
        for (int o = 16; o > 0; o >>= 1) dd += __shfl_xor_sync(0xffffffffu, dd, o);
        if (lane == 0) { ssoft[0] = m; ssoft[1] = 1.f / dd; }
    }
    __syncthreads();
    if (tid < 80) sim[tid] = expf(sim[tid] - ssoft[0]) * ssoft[1];
    __syncthreads();

    float acc = 0.f;
    int d = tid;
    for (int j = 0; j < 80; j++) {
        int r = j >> 4, t = j & 15;
        int skey = sblk[r] * SB_ + t;
        acc += sim[j] * g_qkv[(size_t)skey * NQKV_ + 5120 + h * DH_ + d];
    }
    g_fout[((size_t)i * H_ + qh) * DH_ + d] = acc;
}

// ---------------- sliding-window attention (65 keys, clipped) ----------------
__global__ void slide_attn_kernel() {
    int i = blockIdx.x, qh = blockIdx.y;
    int h = qh >> 2;
    int tid = threadIdx.x;
    int w = tid >> 5, lane = tid & 31;
    __shared__ float sim[65];
    __shared__ float ssoft[2];

    int j0 = i - WIN_;
    if (j0 < 0) j0 = 0;
    int nj = i - j0 + 1;

    const float* qp = g_rq + ((size_t)i * H_ + qh) * DH_;
    float q0 = qp[lane], q1 = qp[lane + 32], q2 = qp[lane + 64], q3 = qp[lane + 96];

    for (int j = w; j < nj; j += 4) {
        int s = j0 + j;
        const float* kp = g_rk + ((size_t)s * KVH_ + h) * DH_;
        float d = q0 * kp[lane] + q1 * kp[lane + 32] + q2 * kp[lane + 64] + q3 * kp[lane + 96];
#pragma unroll
        for (int o = 16; o > 0; o >>= 1) d += __shfl_down_sync(0xffffffffu, d, o);
        if (lane == 0) sim[j] = d * SCALE_;
    }
    __syncthreads();

    if (w == 0) {
        float m = NEGF;
        for (int j = lane; j < nj; j += 32) m = fmaxf(m, sim[j]);
#pragma unroll
        for (int o = 16; o > 0; o >>= 1) m = fmaxf(m, __shfl_xor_sync(0xffffffffu, m, o));
        float dd = 0.f;
        for (int j = lane; j < nj; j += 32) dd += expf(sim[j] - m);
#pragma unroll
        for (int o = 16; o > 0; o >>= 1) dd += __shfl_xor_sync(0xffffffffu, dd, o);
        if (lane == 0) { ssoft[0] = m; ssoft[1] = 1.f / dd; }
    }
    __syncthreads();
    if (tid < nj) sim[tid] = expf(sim[tid] - ssoft[0]) * ssoft[1];
    __syncthreads();

    float acc = 0.f;
    int d = tid;
    for (int j = 0; j < nj; j++)
        acc += sim[j] * g_qkv[(size_t)(j0 + j) * NQKV_ + 5120 + h * DH_ + d];
    g_sout[((size_t)i * H_ + qh) * DH_ + d] = acc;
}

// ---------------- gate-combine ------------------------------------------------
__global__ void combine_kernel() {
    int idx = blockIdx.x * blockDim.x + threadIdx.x;
    if (idx >= S_ * D_) return;
    int i = idx >> 12, hd = idx & 4095, hh = hd >> 7;
    const float* gp = g_gates + i * 96 + hh * 3;
    g_mid[idx] = gp[0] * g_cout[idx] + gp[1] * g_fout[idx] + gp[2] * g_sout[idx];
}

// ---------------- launch ------------------------------------------------------
static inline void run_split(const float* src, __nv_bfloat16* dh,
                             __nv_bfloat16* dl, int n) {
    int n4 = n / 4;
    split_bf16_kernel<<<(n4 + 255) / 256, 256>>>(src, dh, dl, n4);
}

extern "C" void kernel_launch(void* const* d_in, const int* in_sizes, int n_in,
                              void* d_out, int out_size) {
    const float* hidden = (const float*)d_in[0];
    const float* w_qkv  = (const float*)d_in[1];
    const float* w_o    = (const float*)d_in[2];
    const float* k_pos  = (const float*)d_in[3];
    const float* v_pos  = (const float*)d_in[4];
    const float* k_w1   = (const float*)d_in[5];
    const float* k_b1   = (const float*)d_in[6];
    const float* k_w2   = (const float*)d_in[7];
    const float* k_b2   = (const float*)d_in[8];
    const float* v_w1   = (const float*)d_in[9];
    const float* v_b1   = (const float*)d_in[10];
    const float* v_w2   = (const float*)d_in[11];
    const float* v_b2   = (const float*)d_in[12];
    const float* mem_kv = (const float*)d_in[13];
    const float* w_gate = (const float*)d_in[14];
    const float* b_gate = (const float*)d_in[15];
    float* out = (float*)d_out;

    float *qkv, *ckin, *cvin, *h1, *ckb, *cvb, *gates, *mid;
    __nv_bfloat16 *Bh, *Bl, *AXh, *AXl, *ACh, *ACl, *AHh, *AHl;
    cudaGetSymbolAddress((void**)&qkv,   g_qkv);
    cudaGetSymbolAddress((void**)&ckin,  g_ckin);
    cudaGetSymbolAddress((void**)&cvin,  g_cvin);
    cudaGetSymbolAddress((void**)&h1,    g_h1);
    cudaGetSymbolAddress((void**)&ckb,   g_ckb);
    cudaGetSymbolAddress((void**)&cvb,   g_cvb);
    cudaGetSymbolAddress((void**)&gates, g_gates);
    cudaGetSymbolAddress((void**)&mid,   g_mid);
    cudaGetSymbolAddress((void**)&Bh,  g_Bh);
    cudaGetSymbolAddress((void**)&Bl,  g_Bl);
    cudaGetSymbolAddress((void**)&AXh, g_AXh);
    cudaGetSymbolAddress((void**)&AXl, g_AXl);
    cudaGetSymbolAddress((void**)&ACh, g_ACh);
    cudaGetSymbolAddress((void**)&ACl, g_ACl);
    cudaGetSymbolAddress((void**)&AHh, g_AHh);
    cudaGetSymbolAddress((void**)&AHl, g_AHl);

    cudaFuncSetAttribute(gemm_v5<0, false>,
                         cudaFuncAttributeMaxDynamicSharedMemorySize, V5_SMEM_BYTES);
    cudaFuncSetAttribute(gemm_v5<1, false>,
                         cudaFuncAttributeMaxDynamicSharedMemorySize, V5_SMEM_BYTES);
    cudaFuncSetAttribute(gemm_v5<0, true>,
                         cudaFuncAttributeMaxDynamicSharedMemorySize, V5_SMEM_BYTES);

    // 0. rope inverse-frequency table
    invf_kernel<<<1, 64>>>();

    // 1. QKV projection (1024 x 6144 x 4096)
    run_split(hidden, AXh, AXl, S_ * D_);
    run_split(w_qkv, Bh, Bl, NQKV_ * D_);
    gemm_v5<0, false><<<dim3(8, 96, 1), 256, V5_SMEM_BYTES>>>(
        AXh, AXl, Bh, Bl, nullptr, qkv, S_, NQKV_, D_, D_);

    // 2. compressed MLP inputs
    build_cin_kernel<<<(KVH_ * NC_ * CDIM_ + 255) / 256, 256>>>(k_pos, v_pos);

    // 3. K compress MLP: W1 (512 x 2048 x 2048), W2 split-K (512 x 128 x 2048)
    run_split(ckin, ACh, ACl, 512 * CDIM_);
    run_split(k_w1, Bh, Bl, CDIM_ * CDIM_);
    gemm_v5<1, false><<<dim3(4, 32, 1), 256, V5_SMEM_BYTES>>>(
        ACh, ACl, Bh, Bl, k_b1, h1, 512, CDIM_, CDIM_, CDIM_);
    run_split(h1, AHh, AHl, 512 * CDIM_);
    run_split(k_w2, Bh, Bl, DH_ * CDIM_);
    gemm_v5<0, false><<<dim3(4, 2, 8), 256, V5_SMEM_BYTES>>>(
        AHh, AHl, Bh, Bl, nullptr, ckb, 512, DH_, CDIM_, CDIM_ / 8);
    reduce_splitk<0><<<(512 * DH_ + 255) / 256, 256>>>(k_b2, ckb, 512 * DH_, DH_, 8);

    // 4. V compress MLP
    run_split(cvin, ACh, ACl, 512 * CDIM_);
    run_split(v_w1, Bh, Bl, CDIM_ * CDIM_);
    gemm_v5<1, false><<<dim3(4, 32, 1), 256, V5_SMEM_BYTES>>>(
        ACh, ACl, Bh, Bl, v_b1, h1, 512, CDIM_, CDIM_, CDIM_);
    run_split(h1, AHh, AHl, 512 * CDIM_);
    run_split(v_w2, Bh, Bl, DH_ * CDIM_);
    gemm_v5<0, false><<<dim3(4, 2, 8), 256, V5_SMEM_BYTES>>>(
        AHh, AHl, Bh, Bl, nullptr, cvb, 512, DH_, CDIM_, CDIM_ / 8);
    reduce_splitk<0><<<(512 * DH_ + 255) / 256, 256>>>(v_b2, cvb, 512 * DH_, DH_, 8);

    // 5. prepend mem token
    scatter_c_kernel<<<(KVH_ * (NC_ + 1) * DH_ + 255) / 256, 256>>>(mem_kv);
    // 6. RoPE
    rope_kernel<<<S_, 256>>>();
    // 7. compressed attention + selection
    comp_attn_kernel<<<dim3(S_, KVH_), 128>>>();
    // 8. fine attention
    fine_attn_kernel<<<dim3(S_, H_), 128>>>();
    // 9. sliding window attention
    slide_attn_kernel<<<dim3(S_, H_), 128>>>();

    // 10. gates (1024 x 96 x 4096) split-K=16 + sigmoid in reduce
    run_split(w_gate, Bh, Bl, 96 * D_);
    gemm_v5<0, true><<<dim3(8, 2, 16), 256, V5_SMEM_BYTES>>>(
        AXh, AXl, Bh, Bl, nullptr, gates, S_, 96, D_, D_ / 16);
    reduce_splitk<2><<<(S_ * 96 + 255) / 256, 256>>>(b_gate, gates, S_ * 96, 96, 16);

    // 11. combine
    combine_kernel<<<(S_ * D_ + 255) / 256, 256>>>();

    // 12. output projection (1024 x 4096 x 4096); mid reuses hidden's planes
    run_split(mid, AXh, AXl, S_ * D_);
    run_split(w_o, Bh, Bl, D_ * D_);
    gemm_v5<0, false><<<dim3(8, 64, 1), 256, V5_SMEM_BYTES>>>(
        AXh, AXl, Bh, Bl, nullptr, out, S_, D_, D_, D_);
}

// round 17
// speedup vs baseline: 2.0847x; 1.1157x over previous
#include <cuda_runtime.h>
#include <cuda_bf16.h>
#include <math.h>

// ---------------- problem constants ----------------
#define S_   1024
#define H_   32
#define KVH_ 8
#define DH_  128
#define D_   4096
#define CB_  16
#define NC_  64        // S/CB
#define SB_  16
#define NSEL_ 4
#define WIN_ 64
#define NQKV_ 6144     // H*DH + 2*KVH*DH
#define CDIM_ 2048     // CB*DH
#define NEGF (-3.402823466e38f)
#define SCALE_ 0.08838834764831844056f  // 128^-0.5

// ---------------- scratch (no allocs allowed) ----------------
__device__ float g_qkv [S_ * NQKV_];
__device__ float g_rq  [S_ * H_ * DH_];
__device__ float g_rk  [S_ * KVH_ * DH_];
__device__ float g_ckb [KVH_ * NC_ * DH_];
__device__ float g_cvb [KVH_ * NC_ * DH_];
__device__ float g_ck  [KVH_ * (NC_ + 1) * DH_];
__device__ float g_cv  [KVH_ * (NC_ + 1) * DH_];
__device__ float g_cout[S_ * H_ * DH_];
__device__ float g_fout[S_ * H_ * DH_];
__device__ float g_sout[S_ * H_ * DH_];
__device__ int   g_sel [KVH_ * S_ * 5];
__device__ int   g_selok[KVH_ * S_ * 4];
__device__ float g_gates[S_ * 96];
__device__ float g_part[16 * 1024 * 96];   // split-K partials (max: gates)
__device__ float g_invf[64];               // rope inverse frequencies

// bf16 hi/lo planes
__device__ __nv_bfloat16 g_Bh [NQKV_ * D_];   // weights (reused serially)
__device__ __nv_bfloat16 g_Bl [NQKV_ * D_];
__device__ __nv_bfloat16 g_AXh[S_ * D_];      // hidden, later mid
__device__ __nv_bfloat16 g_AXl[S_ * D_];
__device__ __nv_bfloat16 g_ACh [KVH_ * NC_ * CDIM_];   // ckin planes
__device__ __nv_bfloat16 g_ACl [KVH_ * NC_ * CDIM_];
__device__ __nv_bfloat16 g_AC2h[KVH_ * NC_ * CDIM_];   // cvin planes
__device__ __nv_bfloat16 g_AC2l[KVH_ * NC_ * CDIM_];
__device__ __nv_bfloat16 g_AHh[KVH_ * NC_ * CDIM_];    // h1 planes
__device__ __nv_bfloat16 g_AHl[KVH_ * NC_ * CDIM_];

// ---------------- helpers ----------------
__device__ __forceinline__ void mma_bf16(float c[4], const unsigned a[4],
                                         const unsigned b[2]) {
    asm volatile(
        "mma.sync.aligned.m16n8k16.row.col.f32.bf16.bf16.f32 "
        "{%0,%1,%2,%3}, {%4,%5,%6,%7}, {%8,%9}, {%0,%1,%2,%3};\n"
        : "+f"(c[0]), "+f"(c[1]), "+f"(c[2]), "+f"(c[3])
        : "r"(a[0]), "r"(a[1]), "r"(a[2]), "r"(a[3]), "r"(b[0]), "r"(b[1]));
}

__device__ __forceinline__ void cp16(unsigned dst, const void* src, int zfill) {
    asm volatile("cp.async.ca.shared.global [%0], [%1], 16, %2;\n"
                 :: "r"(dst), "l"(src), "r"(zfill));
}

#define LDSM4(R0, R1, R2, R3, ADDR)                                          \
    asm volatile("ldmatrix.sync.aligned.m8n8.x4.shared.b16 {%0,%1,%2,%3},[%4];\n" \
                 : "=r"(R0), "=r"(R1), "=r"(R2), "=r"(R3) : "r"(ADDR))

__device__ __forceinline__ void split1(float v, __nv_bfloat16* ph,
                                       __nv_bfloat16* pl, size_t idx) {
    __nv_bfloat16 h = __float2bfloat16(v);
    ph[idx] = h;
    pl[idx] = __float2bfloat16(v - __bfloat162float(h));
}

// ---------------- hi/lo bf16 split pre-pass (4 floats/thread) ----------------
__global__ void split_bf16_kernel(const float* __restrict__ src,
                                  __nv_bfloat16* __restrict__ dh,
                                  __nv_bfloat16* __restrict__ dl, int n4) {
    int i = blockIdx.x * blockDim.x + threadIdx.x;
    if (i >= n4) return;
    float4 v = ((const float4*)src)[i];
    float x[4] = {v.x, v.y, v.z, v.w};
    unsigned hb[4], lb[4];
#pragma unroll
    for (int j = 0; j < 4; j++) {
        __nv_bfloat16 h = __float2bfloat16(x[j]);
        __nv_bfloat16 l = __float2bfloat16(x[j] - __bfloat162float(h));
        hb[j] = __bfloat16_as_ushort(h);
        lb[j] = __bfloat16_as_ushort(l);
    }
    ((uint2*)dh)[i] = make_uint2((hb[1] << 16) | hb[0], (hb[3] << 16) | hb[2]);
    ((uint2*)dl)[i] = make_uint2((lb[1] << 16) | lb[0], (lb[3] << 16) | lb[2]);
}

// ============ bf16x3 GEMM v6: pre-split planes + m16n8k16 + ldmatrix ========
// C[M,N] = A[M,K] @ B[N,K]^T, 3 products (lo*hi + hi*lo + hi*hi) ~ fp32.
// Tile 128x64x32, 256 thr, warp tile 32x32. smem rows 80B (stride 20 words:
// ldmatrix phases hit banks {20r%32} all-distinct -> conflict-free).
// Fragments via ldmatrix.x4 (A: 16x16/tile; B: two n8k16 per x4).
// OSPLIT: epilogue writes bf16 hi/lo planes instead of fp32 C.
#define V6_SMEM_BYTES 61440

template <int ACT, bool NGUARD, bool OSPLIT>
__global__ void __launch_bounds__(256, 2)
gemm_v6(const __nv_bfloat16* __restrict__ Ah, const __nv_bfloat16* __restrict__ Al,
        const __nv_bfloat16* __restrict__ Bh, const __nv_bfloat16* __restrict__ Bl,
        const float* __restrict__ bias, float* __restrict__ C,
        __nv_bfloat16* __restrict__ Ch, __nv_bfloat16* __restrict__ Cl,
        int M, int N, int K, int klen) {
    extern __shared__ __nv_bfloat16 smb[];

    const int tid = threadIdx.x;
    const int wid = tid >> 5, lane = tid & 31;
    const int warp_m = wid & 3;          // 4 slabs x 32 rows
    const int warp_n = wid >> 2;         // 2 slabs x 32 cols
    const int g = lane >> 2, tg = lane & 3;
    const int bm = blockIdx.x * 128, bn = blockIdx.y * 64;
    const int kglob = blockIdx.z * klen;

    // loaders: A 2 thr/row x 16 bf16 (2x16B per plane); B 4 thr/row x 8 (1x16B)
    const int arow = tid >> 1, acol = (tid & 1) * 16;
    const int brow = tid >> 2, bcol = (tid & 3) * 8;
    int brglob = bn + brow;
    int brc = NGUARD ? (brglob < N ? brglob : N - 1) : brglob;
    const int bzf = (!NGUARD || brglob < N) ? 16 : 0;

    const __nv_bfloat16* Aph = Ah + (size_t)(bm + arow) * K + kglob + acol;
    const __nv_bfloat16* Apl = Al + (size_t)(bm + arow) * K + kglob + acol;
    const __nv_bfloat16* Bph = Bh + (size_t)brc * K + kglob + bcol;
    const __nv_bfloat16* Bpl = Bl + (size_t)brc * K + kglob + bcol;

    const unsigned sbase = (unsigned)__cvta_generic_to_shared(smb);
    const unsigned sa = sbase + (unsigned)(arow * 80 + acol * 2);
    const unsigned sb = sbase + 40960u + (unsigned)(brow * 80 + bcol * 2);

    // ldmatrix per-thread offsets (bytes within a plane)
    const unsigned a_off = (unsigned)((warp_m * 32 + (lane & 15)) * 80 +
                                      ((lane >> 4) << 4));
    const int bseg = lane >> 3;
    const unsigned b_off = (unsigned)((warp_n * 32 + ((bseg >= 2) ? 8 : 0) +
                                       (lane & 7)) * 80 + ((bseg & 1) << 4));

    float acc[2][4][4];
#pragma unroll
    for (int i = 0; i < 2; i++)
#pragma unroll
        for (int j = 0; j < 4; j++)
#pragma unroll
            for (int e = 0; e < 4; e++) acc[i][j][e] = 0.f;

    const int ntiles = klen / 32;

#define V6LOAD(stg, t)                                                       \
    do {                                                                     \
        const __nv_bfloat16* aph = Aph + (t) * 32;                           \
        const __nv_bfloat16* apl = Apl + (t) * 32;                           \
        const __nv_bfloat16* bph = Bph + (t) * 32;                           \
        const __nv_bfloat16* bpl = Bpl + (t) * 32;                           \
        unsigned adh = sa + (stg) * 20480u;                                  \
        unsigned adl = adh + 10240u;                                         \
        unsigned bdh = sb + (stg) * 10240u;                                  \
        unsigned bdl = bdh + 5120u;                                          \
        cp16(adh, aph, 16);        cp16(adh + 16u, aph + 8, 16);             \
        cp16(adl, apl, 16);        cp16(adl + 16u, apl + 8, 16);             \
        cp16(bdh, bph, bzf);       cp16(bdl, bpl, bzf);                      \
        asm volatile("cp.async.commit_group;\n");                            \
    } while (0)

    V6LOAD(0, 0);

    for (int t = 0; t < ntiles; t++) {
        const int stg = t & 1;
        if (t + 1 < ntiles) {
            V6LOAD((t + 1) & 1, t + 1);
            asm volatile("cp.async.wait_group 1;\n");
        } else {
            asm volatile("cp.async.wait_group 0;\n");
        }
        __syncthreads();

        const unsigned aH = sbase + stg * 20480u + a_off;
        const unsigned aL = aH + 10240u;
        const unsigned bH = sbase + 40960u + stg * 10240u + b_off;
        const unsigned bL = bH + 5120u;

#pragma unroll
        for (int ks = 0; ks < 2; ks++) {
            const unsigned kb = ks * 32u;
            unsigned ah[2][4], al[2][4], bh[4][2], bl[4][2];
#pragma unroll
            for (int mt = 0; mt < 2; mt++) {
                LDSM4(ah[mt][0], ah[mt][1], ah[mt][2], ah[mt][3],
                      aH + kb + mt * 1280u);
                LDSM4(al[mt][0], al[mt][1], al[mt][2], al[mt][3],
                      aL + kb + mt * 1280u);
            }
#pragma unroll
            for (int p = 0; p < 2; p++) {
                LDSM4(bh[2 * p][0], bh[2 * p][1], bh[2 * p + 1][0],
                      bh[2 * p + 1][1], bH + kb + p * 1280u);
                LDSM4(bl[2 * p][0], bl[2 * p][1], bl[2 * p + 1][0],
                      bl[2 * p + 1][1], bL + kb + p * 1280u);
            }
#pragma unroll
            for (int mt = 0; mt < 2; mt++)
#pragma unroll
                for (int nt = 0; nt < 4; nt++) {
                    mma_bf16(acc[mt][nt], al[mt], bh[nt]);
                    mma_bf16(acc[mt][nt], ah[mt], bl[nt]);
                    mma_bf16(acc[mt][nt], ah[mt], bh[nt]);
                }
        }
        __syncthreads();
    }
#undef V6LOAD

    const bool split = (gridDim.z > 1);
#pragma unroll
    for (int mt = 0; mt < 2; mt++) {
#pragma unroll
        for (int nt = 0; nt < 4; nt++) {
#pragma unroll
            for (int e = 0; e < 4; e++) {
                int row = bm + warp_m * 32 + mt * 16 + g + ((e >= 2) ? 8 : 0);
                int col = bn + warp_n * 32 + nt * 8 + 2 * tg + (e & 1);
                if (NGUARD && col >= N) continue;
                float v = acc[mt][nt][e];
                if (split) {
                    g_part[(size_t)blockIdx.z * M * N + (size_t)row * N + col] = v;
                } else {
                    if (bias) v += bias[col];
                    if (ACT == 1) v = fmaxf(v, 0.f);
                    if (OSPLIT) {
                        split1(v, Ch, Cl, (size_t)row * N + col);
                    } else {
                        C[(size_t)row * N + col] = v;
                    }
                }
            }
        }
    }
}

// split-K reduce: C = act(sum_z part + bias). ACT: 0 none, 2 sigmoid
template <int ACT>
__global__ void reduce_splitk(const float* __restrict__ bias,
                              float* __restrict__ C, int MN, int N, int splits) {
    int idx = blockIdx.x * blockDim.x + threadIdx.x;
    if (idx >= MN) return;
    float s = 0.f;
    for (int z = 0; z < splits; z++) s += g_part[(size_t)z * MN + idx];
    if (bias) s += bias[idx % N];
    if (ACT == 2) s = 1.f / (1.f + expf(-s));
    C[idx] = s;
}

// ---------------- build compressed MLP inputs (writes bf16 planes) -----------
__global__ void build_cin_kernel(const float* __restrict__ k_pos,
                                 const float* __restrict__ v_pos) {
    int idx = blockIdx.x * blockDim.x + threadIdx.x;
    if (idx >= KVH_ * NC_ * CDIM_) return;
    int r = idx >> 11, col = idx & 2047;
    int h = r >> 6, c = r & 63;
    int t = col >> 7, d = col & 127;
    int s = c * CB_ + t;
    size_t base = (size_t)s * NQKV_ + h * DH_ + d;
    int pidx = (h * CB_ + t) * DH_ + d;
    float kv = g_qkv[base + 4096] + k_pos[pidx];
    float vv = g_qkv[base + 5120] + v_pos[pidx];
    split1(kv, g_ACh, g_ACl, idx);
    split1(vv, g_AC2h, g_AC2l, idx);
}

// ---------------- scatter compressed K/V (prepend mem token) -----------------
__global__ void scatter_c_kernel(const float* __restrict__ mem_kv) {
    int idx = blockIdx.x * blockDim.x + threadIdx.x;
    if (idx >= KVH_ * (NC_ + 1) * DH_) return;
    int d = idx & 127, jh = idx >> 7;
    int h = jh / (NC_ + 1), j = jh % (NC_ + 1);
    float kv, vv;
    if (j == 0) {
        kv = mem_kv[h * DH_ + d];
        vv = mem_kv[KVH_ * DH_ + h * DH_ + d];
    } else {
        int r = (h * NC_ + (j - 1)) * DH_ + d;
        kv = g_ckb[r];
        vv = g_cvb[r];
    }
    g_ck[idx] = kv;
    g_cv[idx] = vv;
}

// ---------------- RoPE (interleaved, theta=10000) ----------------------------
__global__ void invf_kernel() {
    int p = threadIdx.x;
    g_invf[p] = (float)pow(10000.0, -(double)(2 * p) / 128.0);
}

__global__ void rope_kernel() {     // grid: S_, block: 256
    __shared__ float cs_[64], sn_[64];
    int i = blockIdx.x, tid = threadIdx.x;
    if (tid < 64) {
        float ang = (float)i * g_invf[tid];
        sincosf(ang, &sn_[tid], &cs_[tid]);
    }
    __syncthreads();
    for (int u = tid; u < (H_ + KVH_) * 64; u += 256) {
        int y = u >> 6, p = u & 63;
        const float* src;
        float* dst;
        if (y < H_) {
            src = g_qkv + (size_t)i * NQKV_ + y * DH_;
            dst = g_rq + ((size_t)i * H_ + y) * DH_;
        } else {
            src = g_qkv + (size_t)i * NQKV_ + 4096 + (y - H_) * DH_;
            dst = g_rk + ((size_t)i * KVH_ + (y - H_)) * DH_;
        }
        float x0 = src[2 * p], x1 = src[2 * p + 1];
        dst[2 * p]     = x0 * cs_[p] - x1 * sn_[p];
        dst[2 * p + 1] = x1 * cs_[p] + x0 * sn_[p];
    }
}

// ---------------- compressed attention + importance top-k --------------------
__global__ void comp_attn_kernel() {
    int i = blockIdx.x;
    int h = blockIdx.y;
    int tid = threadIdx.x;
    int g = tid >> 5, lane = tid & 31;
    __shared__ float sim[4][65];
    __shared__ float imp[64];
    __shared__ float prob[64];
    __shared__ float red[2];

    const float* qp = g_qkv + (size_t)i * NQKV_ + (h * 4 + g) * DH_;
    float q0 = qp[lane], q1 = qp[lane + 32], q2 = qp[lane + 64], q3 = qp[lane + 96];

    for (int j = 0; j < 65; j++) {
        const float* kp = g_ck + (h * 65 + j) * DH_;
        float d = q0 * kp[lane] + q1 * kp[lane + 32] + q2 * kp[lane + 64] + q3 * kp[lane + 96];
#pragma unroll
        for (int o = 16; o > 0; o >>= 1) d += __shfl_down_sync(0xffffffffu, d, o);
        if (lane == 0) {
            bool vis = (j == 0) || (i >= j * CB_);
            sim[g][j] = vis ? d * SCALE_ : NEGF;
        }
    }
    __syncwarp();

    float m = NEGF;
    for (int j = lane; j < 65; j += 32) m = fmaxf(m, sim[g][j]);
#pragma unroll
    for (int o = 16; o > 0; o >>= 1) m = fmaxf(m, __shfl_xor_sync(0xffffffffu, m, o));
    float den = 0.f;
    for (int j = lane; j < 65; j += 32) den += expf(sim[g][j] - m);
#pragma unroll
    for (int o = 16; o > 0; o >>= 1) den += __shfl_xor_sync(0xffffffffu, den, o);
    float invden = 1.f / den;

    float o0 = 0, o1 = 0, o2 = 0, o3 = 0;
    for (int j = 0; j < 65; j++) {
        float p = expf(sim[g][j] - m) * invden;
        const float* vp = g_cv + (h * 65 + j) * DH_;
        o0 += p * vp[lane];
        o1 += p * vp[lane + 32];
        o2 += p * vp[lane + 64];
        o3 += p * vp[lane + 96];
    }
    float* op = g_cout + ((size_t)i * H_ + h * 4 + g) * DH_;
    op[lane] = o0; op[lane + 32] = o1; op[lane + 64] = o2; op[lane + 96] = o3;

    __syncthreads();

    if (tid < 64) {
        float s = sim[0][tid + 1] + sim[1][tid + 1] + sim[2][tid + 1] + sim[3][tid + 1];
        imp[tid] = 0.25f * s;
    }
    __syncthreads();

    if (tid == 0) {
        float mm = -1000.f;
        for (int j = 0; j < 64; j++) mm = fmaxf(mm, imp[j]);
        float dd = expf(-1000.f - mm);
        for (int j = 0; j < 64; j++) dd += expf(imp[j] - mm);
        red[0] = mm;
        red[1] = 1.f / dd;
    }
    __syncthreads();
    if (tid < 64) prob[tid] = expf(imp[tid] - red[0]) * red[1];
    __syncthreads();

    if (tid == 0) {
        unsigned long long used = 0ull;
        int* sp = g_sel + (h * S_ + i) * 5;
        int* okp = g_selok + (h * S_ + i) * 4;
        for (int r = 0; r < NSEL_; r++) {
            float bp = -1.f;
            int bj = 0;
            for (int j = 0; j < 64; j++) {
                if ((used >> j) & 1ull) continue;
                float p = prob[j];
                if (p > bp) { bp = p; bj = j; }   // strict > : lowest-index tiebreak
            }
            used |= 1ull << bj;
            sp[r] = bj;
            okp[r] = (bp > 1e-10f) ? 1 : 0;
        }
        sp[4] = i >> 4;
    }
}

// ---------------- fine (selected-block) attention ----------------------------
__global__ void fine_attn_kernel() {
    int i = blockIdx.x, qh = blockIdx.y;
    int h = qh >> 2;
    int tid = threadIdx.x;
    int w = tid >> 5, lane = tid & 31;
    __shared__ float sim[80];
    __shared__ int sblk[5];
    __shared__ int sok[4];
    __shared__ float ssoft[2];

    if (tid < 5) sblk[tid] = g_sel[(h * S_ + i) * 5 + tid];
    if (tid < 4) sok[tid] = g_selok[(h * S_ + i) * 4 + tid];
    __syncthreads();

    const float* qp = g_rq + ((size_t)i * H_ + qh) * DH_;
    float q0 = qp[lane], q1 = qp[lane + 32], q2 = qp[lane + 64], q3 = qp[lane + 96];

    for (int j = w * 20; j < w * 20 + 20; j++) {
        int r = j >> 4, t = j & 15;
        int skey = sblk[r] * SB_ + t;
        const float* kp = g_rk + ((size_t)skey * KVH_ + h) * DH_;
        float d = q0 * kp[lane] + q1 * kp[lane + 32] + q2 * kp[lane + 64] + q3 * kp[lane + 96];
#pragma unroll
        for (int o = 16; o > 0; o >>= 1) d += __shfl_down_sync(0xffffffffu, d, o);
        if (lane == 0) {
            bool vis = (r < 4) ? (sok[r] != 0) : (t <= (i & 15));
            sim[j] = vis ? d * SCALE_ : NEGF;
        }
    }
    __syncthreads();

    if (w == 0) {
        float m = NEGF;
        for (int j = lane; j < 80; j += 32) m = fmaxf(m, sim[j]);
#pragma unroll
        for (int o = 16; o > 0; o >>= 1) m = fmaxf(m, __shfl_xor_sync(0xffffffffu, m, o));
        float dd = 0.f;
        for (int j = lane; j < 80; j += 32) dd += expf(sim[j] - m);
#pragma unroll
        for (int o = 16; o > 0; o >>= 1) dd += __shfl_xor_sync(0xffffffffu, dd, o);
        if (lane == 0) { ssoft[0] = m; ssoft[1] = 1.f / dd; }
    }
    __syncthreads();
    if (tid < 80) sim[tid] = expf(sim[tid] - ssoft[0]) * ssoft[1];
    __syncthreads();

    float acc = 0.f;
    int d = tid;
    for (int j = 0; j < 80; j++) {
        int r = j >> 4, t = j & 15;
        int skey = sblk[r] * SB_ + t;
        acc += sim[j] * g_qkv[(size_t)skey * NQKV_ + 5120 + h * DH_ + d];
    }
    g_fout[((size_t)i * H_ + qh) * DH_ + d] = acc;
}

// ---------------- sliding-window attention (65 keys, clipped) ----------------
__global__ void slide_attn_kernel() {
    int i = blockIdx.x, qh = blockIdx.y;
    int h = qh >> 2;
    int tid = threadIdx.x;
    int w = tid >> 5, lane = tid & 31;
    __shared__ float sim[65];
    __shared__ float ssoft[2];

    int j0 = i - WIN_;
    if (j0 < 0) j0 = 0;
    int nj = i - j0 + 1;

    const float* qp = g_rq + ((size_t)i * H_ + qh) * DH_;
    float q0 = qp[lane], q1 = qp[lane + 32], q2 = qp[lane + 64], q3 = qp[lane + 96];

    for (int j = w; j < nj; j += 4) {
        int s = j0 + j;
        const float* kp = g_rk + ((size_t)s * KVH_ + h) * DH_;
        float d = q0 * kp[lane] + q1 * kp[lane + 32] + q2 * kp[lane + 64] + q3 * kp[lane + 96];
#pragma unroll
        for (int o = 16; o > 0; o >>= 1) d += __shfl_down_sync(0xffffffffu, d, o);
        if (lane == 0) sim[j] = d * SCALE_;
    }
    __syncthreads();

    if (w == 0) {
        float m = NEGF;
        for (int j = lane; j < nj; j += 32) m = fmaxf(m, sim[j]);
#pragma unroll
        for (int o = 16; o > 0; o >>= 1) m = fmaxf(m, __shfl_xor_sync(0xffffffffu, m, o));
        float dd = 0.f;
        for (int j = lane; j < nj; j += 32) dd += expf(sim[j] - m);
#pragma unroll
        for (int o = 16; o > 0; o >>= 1) dd += __shfl_xor_sync(0xffffffffu, dd, o);
        if (lane == 0) { ssoft[0] = m; ssoft[1] = 1.f / dd; }
    }
    __syncthreads();
    if (tid < nj) sim[tid] = expf(sim[tid] - ssoft[0]) * ssoft[1];
    __syncthreads();

    float acc = 0.f;
    int d = tid;
    for (int j = 0; j < nj; j++)
        acc += sim[j] * g_qkv[(size_t)(j0 + j) * NQKV_ + 5120 + h * DH_ + d];
    g_sout[((size_t)i * H_ + qh) * DH_ + d] = acc;
}

// ---------------- gate-combine (writes mid's bf16 planes directly) -----------
__global__ void combine_kernel() {
    int idx = blockIdx.x * blockDim.x + threadIdx.x;
    if (idx >= S_ * D_) return;
    int i = idx >> 12, hd = idx & 4095, hh = hd >> 7;
    const float* gp = g_gates + i * 96 + hh * 3;
    float v = gp[0] * g_cout[idx] + gp[1] * g_fout[idx] + gp[2] * g_sout[idx];
    split1(v, g_AXh, g_AXl, idx);
}

// ---------------- launch ------------------------------------------------------
static inline void run_split(const float* src, __nv_bfloat16* dh,
                             __nv_bfloat16* dl, int n) {
    int n4 = n / 4;
    split_bf16_kernel<<<(n4 + 255) / 256, 256>>>(src, dh, dl, n4);
}

extern "C" void kernel_launch(void* const* d_in, const int* in_sizes, int n_in,
                              void* d_out, int out_size) {
    const float* hidden = (const float*)d_in[0];
    const float* w_qkv  = (const float*)d_in[1];
    const float* w_o    = (const float*)d_in[2];
    const float* k_pos  = (const float*)d_in[3];
    const float* v_pos  = (const float*)d_in[4];
    const float* k_w1   = (const float*)d_in[5];
    const float* k_b1   = (const float*)d_in[6];
    const float* k_w2   = (const float*)d_in[7];
    const float* k_b2   = (const float*)d_in[8];
    const float* v_w1   = (const float*)d_in[9];
    const float* v_b1   = (const float*)d_in[10];
    const float* v_w2   = (const float*)d_in[11];
    const float* v_b2   = (const float*)d_in[12];
    const float* mem_kv = (const float*)d_in[13];
    const float* w_gate = (const float*)d_in[14];
    const float* b_gate = (const float*)d_in[15];
    float* out = (float*)d_out;

    float *qkv, *ckb, *cvb, *gates;
    __nv_bfloat16 *Bh, *Bl, *AXh, *AXl, *ACh, *ACl, *AC2h, *AC2l, *AHh, *AHl;
    cudaGetSymbolAddress((void**)&qkv,   g_qkv);
    cudaGetSymbolAddress((void**)&ckb,   g_ckb);
    cudaGetSymbolAddress((void**)&cvb,   g_cvb);
    cudaGetSymbolAddress((void**)&gates, g_gates);
    cudaGetSymbolAddress((void**)&Bh,   g_Bh);
    cudaGetSymbolAddress((void**)&Bl,   g_Bl);
    cudaGetSymbolAddress((void**)&AXh,  g_AXh);
    cudaGetSymbolAddress((void**)&AXl,  g_AXl);
    cudaGetSymbolAddress((void**)&ACh,  g_ACh);
    cudaGetSymbolAddress((void**)&ACl,  g_ACl);
    cudaGetSymbolAddress((void**)&AC2h, g_AC2h);
    cudaGetSymbolAddress((void**)&AC2l, g_AC2l);
    cudaGetSymbolAddress((void**)&AHh,  g_AHh);
    cudaGetSymbolAddress((void**)&AHl,  g_AHl);

    cudaFuncSetAttribute(gemm_v6<0, false, false>,
                         cudaFuncAttributeMaxDynamicSharedMemorySize, V6_SMEM_BYTES);
    cudaFuncSetAttribute(gemm_v6<1, false, true>,
                         cudaFuncAttributeMaxDynamicSharedMemorySize, V6_SMEM_BYTES);
    cudaFuncSetAttribute(gemm_v6<0, true, false>,
                         cudaFuncAttributeMaxDynamicSharedMemorySize, V6_SMEM_BYTES);

    // 0. rope inverse-frequency table
    invf_kernel<<<1, 64>>>();

    // 1. QKV projection (1024 x 6144 x 4096)
    run_split(hidden, AXh, AXl, S_ * D_);
    run_split(w_qkv, Bh, Bl, NQKV_ * D_);
    gemm_v6<0, false, false><<<dim3(8, 96, 1), 256, V6_SMEM_BYTES>>>(
        AXh, AXl, Bh, Bl, nullptr, qkv, nullptr, nullptr, S_, NQKV_, D_, D_);

    // 2. compressed MLP inputs -> bf16 planes directly
    build_cin_kernel<<<(KVH_ * NC_ * CDIM_ + 255) / 256, 256>>>(k_pos, v_pos);

    // 3. K compress MLP: W1 (512 x 2048 x 2048, relu, split-out), W2 split-K
    run_split(k_w1, Bh, Bl, CDIM_ * CDIM_);
    gemm_v6<1, false, true><<<dim3(4, 32, 1), 256, V6_SMEM_BYTES>>>(
        ACh, ACl, Bh, Bl, k_b1, nullptr, AHh, AHl, 512, CDIM_, CDIM_, CDIM_);
    run_split(k_w2, Bh, Bl, DH_ * CDIM_);
    gemm_v6<0, false, false><<<dim3(4, 2, 8), 256, V6_SMEM_BYTES>>>(
        AHh, AHl, Bh, Bl, nullptr, ckb, nullptr, nullptr, 512, DH_, CDIM_, CDIM_ / 8);
    reduce_splitk<0><<<(512 * DH_ + 255) / 256, 256>>>(k_b2, ckb, 512 * DH_, DH_, 8);

    // 4. V compress MLP
    run_split(v_w1, Bh, Bl, CDIM_ * CDIM_);
    gemm_v6<1, false, true><<<dim3(4, 32, 1), 256, V6_SMEM_BYTES>>>(
        AC2h, AC2l, Bh, Bl, v_b1, nullptr, AHh, AHl, 512, CDIM_, CDIM_, CDIM_);
    run_split(v_w2, Bh, Bl, DH_ * CDIM_);
    gemm_v6<0, false, false><<<dim3(4, 2, 8), 256, V6_SMEM_BYTES>>>(
        AHh, AHl, Bh, Bl, nullptr, cvb, nullptr, nullptr, 512, DH_, CDIM_, CDIM_ / 8);
    reduce_splitk<0><<<(512 * DH_ + 255) / 256, 256>>>(v_b2, cvb, 512 * DH_, DH_, 8);

    // 5. prepend mem token
    scatter_c_kernel<<<(KVH_ * (NC_ + 1) * DH_ + 255) / 256, 256>>>(mem_kv);
    // 6. RoPE
    rope_kernel<<<S_, 256>>>();
    // 7. compressed attention + selection
    comp_attn_kernel<<<dim3(S_, KVH_), 128>>>();
    // 8. fine attention
    fine_attn_kernel<<<dim3(S_, H_), 128>>>();
    // 9. sliding window attention
    slide_attn_kernel<<<dim3(S_, H_), 128>>>();

    // 10. gates (1024 x 96 x 4096) split-K=16 + sigmoid in reduce
    //     (uses hidden's planes; must precede combine overwriting AX planes)
    run_split(w_gate, Bh, Bl, 96 * D_);
    gemm_v6<0, true, false><<<dim3(8, 2, 16), 256, V6_SMEM_BYTES>>>(
        AXh, AXl, Bh, Bl, nullptr, gates, nullptr, nullptr, S_, 96, D_, D_ / 16);
    reduce_splitk<2><<<(S_ * 96 + 255) / 256, 256>>>(b_gate, gates, S_ * 96, 96, 16);

    // 11. combine -> writes mid planes (AXh/AXl) directly
    combine_kernel<<<(S_ * D_ + 255) / 256, 256>>>();

    // 12. output projection (1024 x 4096 x 4096)
    run_split(w_o, Bh, Bl, D_ * D_);
    gemm_v6<0, false, false><<<dim3(8, 64, 1), 256, V6_SMEM_BYTES>>>(
        AXh, AXl, Bh, Bl, nullptr, out, nullptr, nullptr, S_, D_, D_, D_);
}